// round 7
// baseline (speedup 1.0000x reference)
#include <cuda_runtime.h>
#include <cuda_bf16.h>
#include <math.h>
#include <stdint.h>

#define Bq 4
#define Sq 2048
#define Eq 1024
#define ROWB 144    // 64 bf16 = 128B data + 16B pad per smem row

// ---------------- scratch ----------------
__device__ __align__(256) __nv_bfloat16 g_xa[8192LL * 3072];      // x_q A-aug
__device__ __align__(256) __nv_bfloat16 g_wka[1024LL * 3072];     // Wk A-aug
__device__ __align__(256) __nv_bfloat16 g_wqb[1024LL * 3072];     // Wq B-aug
__device__ __align__(256) __nv_bfloat16 g_mb[1024LL * 3072];      // M' B-aug
__device__ __align__(256) __nv_bfloat16 g_wvb[1024LL * 3072];     // Wv^T B-aug
__device__ float g_mpart[4LL * 1024 * 1024];                      // M' split-K partials
__device__ __align__(256) __nv_bfloat16 g_ta[8192LL * 3072];      // t A-aug, then u A-aug
__device__ __align__(256) __nv_bfloat16 g_ka[4LL * 2048 * 3072];  // keys B-aug per batch
__device__ __align__(256) __nv_bfloat16 g_va[4LL * 1024 * 6144];  // values^T B-aug per batch
__device__ __align__(256) __nv_bfloat16 g_pa[8192LL * 6144];      // P A-aug
__device__ float g_s[(size_t)Bq * Sq * Sq];                       // fp32 logits

// ---------------- helpers ----------------
__device__ __forceinline__ uint32_t smem_u32(const void* p) {
    uint32_t a;
    asm("{ .reg .u64 t; cvta.to.shared.u64 t, %1; cvt.u32.u64 %0, t; }" : "=r"(a) : "l"(p));
    return a;
}
__device__ __forceinline__ void cpasync16(uint32_t dst, const void* src) {
    asm volatile("cp.async.cg.shared.global [%0], [%1], 16;" :: "r"(dst), "l"(src));
}
__device__ __forceinline__ void split2(float v, __nv_bfloat16& h, __nv_bfloat16& l) {
    h = __float2bfloat16(v);
    l = __float2bfloat16(v - __bfloat162float(h));
}
__device__ __forceinline__ void mma16816(float* d, const uint32_t* a, const uint32_t* b) {
    asm volatile(
        "mma.sync.aligned.m16n8k16.row.col.f32.bf16.bf16.f32 "
        "{%0,%1,%2,%3}, {%4,%5,%6,%7}, {%8,%9}, {%0,%1,%2,%3};"
        : "+f"(d[0]), "+f"(d[1]), "+f"(d[2]), "+f"(d[3])
        : "r"(a[0]), "r"(a[1]), "r"(a[2]), "r"(a[3]), "r"(b[0]), "r"(b[1]));
}
__device__ __forceinline__ void ldsm4(uint32_t* r, uint32_t a) {
    asm volatile("ldmatrix.sync.aligned.m8n8.x4.shared.b16 {%0,%1,%2,%3}, [%4];"
                 : "=r"(r[0]), "=r"(r[1]), "=r"(r[2]), "=r"(r[3]) : "r"(a));
}

// ---------------- split fp32 -> augmented bf16 (row-major [R, 3K]) ----------------
// A-pattern slots {k,K+k,2K+k} = {hi,hi,lo}; B-pattern = {hi,lo,hi}. TRANS: dst[r][k]=src[k][r].
template <bool APAT, bool TRANS>
__global__ __launch_bounds__(256) void split_aug(const float* __restrict__ src,
                                                 __nv_bfloat16* __restrict__ dst,
                                                 int Rout, int K, long long sZ, long long dZ) {
    src += blockIdx.y * sZ;
    dst += blockIdx.y * dZ;
    long long idx = (long long)blockIdx.x * 256 + threadIdx.x;
    int row, kp;
    float v0, v1;
    if (TRANS) {
        row = (int)(idx % Rout);
        kp = (int)(idx / Rout) * 2;
        v0 = src[(long long)kp * Rout + row];
        v1 = src[(long long)(kp + 1) * Rout + row];
    } else {
        const int hk = K >> 1;
        row = (int)(idx / hk);
        kp = (int)(idx % hk) * 2;
        v0 = src[(long long)row * K + kp];
        v1 = src[(long long)row * K + kp + 1];
    }
    __nv_bfloat16 h0, l0, h1, l1;
    split2(v0, h0, l0);
    split2(v1, h1, l1);
    __nv_bfloat162 H, L;
    H.x = h0; H.y = h1;
    L.x = l0; L.y = l1;
    __nv_bfloat162* d = (__nv_bfloat162*)(dst + (long long)row * 3 * K);
    d[kp >> 1] = H;
    d[(K + kp) >> 1] = APAT ? H : L;
    d[(2 * K + kp) >> 1] = APAT ? L : H;
}

// ---------------- reduce 4 split-K partials -> B-aug (hi,lo,hi), M'[1024,1024] ----------------
__global__ __launch_bounds__(256) void reduce4_bsplit(const float* __restrict__ p,
                                                      __nv_bfloat16* __restrict__ d) {
    int i = blockIdx.x * 256 + threadIdx.x;       // 0..524287
    int e2 = i >> 9;
    int e1 = (i & 511) * 2;
    long long o = (long long)e2 * 1024 + e1;
    float v0 = p[o] + p[o + (1 << 20)] + p[o + (2 << 20)] + p[o + (3 << 20)];
    float v1 = p[o + 1] + p[o + 1 + (1 << 20)] + p[o + 1 + (2 << 20)] + p[o + 1 + (3 << 20)];
    __nv_bfloat16 h0, l0, h1, l1;
    split2(v0, h0, l0);
    split2(v1, h1, l1);
    __nv_bfloat162 H, L;
    H.x = h0; H.y = h1;
    L.x = l0; L.y = l1;
    __nv_bfloat162* q = (__nv_bfloat162*)(d + (long long)e2 * 3072);
    q[e1 >> 1] = H;
    q[(1024 + e1) >> 1] = L;
    q[(2048 + e1) >> 1] = H;
}

// ---------------- pipelined bf16 mma.sync GEMM, tile (32*IT) x (32*JN) ----------------
// C = A[M,Kp-stride] @ B[N,Kp-stride]^T over 64*kiters K elems.
// EPI 0: f32 to Cf (+z*cZ); EPI 1: A-aug (hi,hi,lo) to aux (+z*cZ) at [row*3072 + {n,1024+n,2048+n}]
template <int EPI, int IT, int JN, int STG>
__global__ __launch_bounds__(256, 1)
void gemm_bf16(const __nv_bfloat16* __restrict__ A, const __nv_bfloat16* __restrict__ B,
               float* __restrict__ Cf, __nv_bfloat16* __restrict__ aux,
               int N, int Kp, int kiters, long long aZ, long long bZ, long long cZ) {
    constexpr int AROWS = 32 * IT, BROWS = 32 * JN;
    constexpr int STB = (AROWS + BROWS) * ROWB;
    extern __shared__ char smem[];
    const uint32_t sb = smem_u32(smem);
    const int tid = threadIdx.x;
    const int lane = tid & 31, g = lane >> 2, c = lane & 3;
    const int wid = tid >> 5, wm = wid & 1, wn = wid >> 1;

    const char* Ab = (const char*)(A + blockIdx.z * aZ + (long long)(blockIdx.y * AROWS) * Kp);
    const char* Bb = (const char*)(B + blockIdx.z * bZ + (long long)(blockIdx.x * BROWS) * Kp);
    const long long rowbytes = (long long)Kp * 2;

    uint32_t aOff[IT], bOff[JN / 2];
#pragma unroll
    for (int i = 0; i < IT; i++)
        aOff[i] = (wm * (16 * IT) + i * 16 + (lane & 7) + 8 * ((lane >> 3) & 1)) * ROWB
                  + 16 * ((lane >> 4) & 1);
#pragma unroll
    for (int jp = 0; jp < JN / 2; jp++)
        bOff[jp] = (AROWS + wn * (8 * JN) + jp * 16 + (lane & 7) + 8 * ((lane >> 4) & 1)) * ROWB
                   + 16 * ((lane >> 3) & 1);

    auto load_stage = [&](int s, int ck, bool active) {
        if (active) {
            uint32_t d0 = sb + s * STB;
            long long off = (long long)ck * 128;
#pragma unroll
            for (int t = 0; t < IT; t++) {
                int idx = tid + 256 * t, r = idx >> 3, sg = (idx & 7) * 16;
                cpasync16(d0 + r * ROWB + sg, Ab + (long long)r * rowbytes + off + sg);
            }
#pragma unroll
            for (int t = IT; t < IT + JN; t++) {
                int idx = tid + 256 * t, r = idx >> 3, sg = (idx & 7) * 16;
                cpasync16(d0 + r * ROWB + sg, Bb + (long long)(r - AROWS) * rowbytes + off + sg);
            }
        }
        asm volatile("cp.async.commit_group;");
    };

    float acc[IT][JN][4];
#pragma unroll
    for (int i = 0; i < IT; i++)
#pragma unroll
        for (int j = 0; j < JN; j++)
#pragma unroll
            for (int r = 0; r < 4; r++) acc[i][j][r] = 0.0f;

#pragma unroll
    for (int s = 0; s < STG - 1; s++) load_stage(s, s, s < kiters);

    for (int k = 0; k < kiters; k++) {
        asm volatile("cp.async.wait_group %0;" :: "n"(STG - 2));
        __syncthreads();
        const uint32_t sk = sb + (k % STG) * STB;
#pragma unroll
        for (int ks = 0; ks < 4; ks++) {
            uint32_t af[IT][4], bfr[JN][2];
#pragma unroll
            for (int i = 0; i < IT; i++) ldsm4(af[i], sk + aOff[i] + ks * 32);
#pragma unroll
            for (int jp = 0; jp < JN / 2; jp++) {
                uint32_t q[4];
                ldsm4(q, sk + bOff[jp] + ks * 32);
                bfr[2 * jp][0] = q[0];
                bfr[2 * jp][1] = q[1];
                bfr[2 * jp + 1][0] = q[2];
                bfr[2 * jp + 1][1] = q[3];
            }
#pragma unroll
            for (int i = 0; i < IT; i++)
#pragma unroll
                for (int j = 0; j < JN; j++) mma16816(acc[i][j], af[i], bfr[j]);
        }
        __syncthreads();
        const int nk = k + STG - 1;
        load_stage(nk % STG, nk, nk < kiters);
    }

#pragma unroll
    for (int i = 0; i < IT; i++) {
#pragma unroll
        for (int j = 0; j < JN; j++) {
            const int r0 = blockIdx.y * AROWS + wm * (16 * IT) + i * 16 + g;
            const int n0 = blockIdx.x * BROWS + wn * (8 * JN) + j * 8 + 2 * c;
            if (EPI == 0) {
                float* Cb = Cf + blockIdx.z * cZ;
                float2 lo, hi;
                lo.x = acc[i][j][0]; lo.y = acc[i][j][1];
                hi.x = acc[i][j][2]; hi.y = acc[i][j][3];
                *(float2*)&Cb[(long long)r0 * N + n0] = lo;
                *(float2*)&Cb[(long long)(r0 + 8) * N + n0] = hi;
            } else {
                __nv_bfloat16* ab = aux + blockIdx.z * cZ;
#pragma unroll
                for (int rr = 0; rr < 2; rr++) {
                    const int row = r0 + 8 * rr;
                    __nv_bfloat16 h0, l0, h1, l1;
                    split2(acc[i][j][2 * rr], h0, l0);
                    split2(acc[i][j][2 * rr + 1], h1, l1);
                    __nv_bfloat162 H, L;
                    H.x = h0; H.y = h1;
                    L.x = l0; L.y = l1;
                    __nv_bfloat162* p2 = (__nv_bfloat162*)(ab + (long long)row * 3072);
                    p2[n0 >> 1] = H;
                    p2[(1024 + n0) >> 1] = H;
                    p2[(2048 + n0) >> 1] = L;
                }
            }
        }
    }
}

// ---------------- softmax + /32, writing P A-aug [row, 6144] ----------------
__global__ __launch_bounds__(256) void softmax_aug(const float* __restrict__ S,
                                                   __nv_bfloat16* __restrict__ pa) {
    const float* row = S + (long long)blockIdx.x * Sq;
    __nv_bfloat16* d = pa + (long long)blockIdx.x * 6144;
    const int tid = threadIdx.x;
    float vals[8], m = -INFINITY;
#pragma unroll
    for (int i = 0; i < 8; i++) { vals[i] = row[tid + i * 256]; m = fmaxf(m, vals[i]); }
    __shared__ float red[256];
    red[tid] = m;
    __syncthreads();
    for (int s = 128; s > 0; s >>= 1) { if (tid < s) red[tid] = fmaxf(red[tid], red[tid + s]); __syncthreads(); }
    m = red[0];
    __syncthreads();
    float sum = 0.f;
#pragma unroll
    for (int i = 0; i < 8; i++) { vals[i] = expf(vals[i] - m); sum += vals[i]; }
    red[tid] = sum;
    __syncthreads();
    for (int s = 128; s > 0; s >>= 1) { if (tid < s) red[tid] += red[tid + s]; __syncthreads(); }
    const float inv = 1.0f / (red[0] * 32.0f);
#pragma unroll
    for (int i = 0; i < 8; i++) {
        const int j = tid + i * 256;
        __nv_bfloat16 h, l;
        split2(vals[i] * inv, h, l);
        d[j] = h;
        d[2048 + j] = h;
        d[4096 + j] = l;
    }
}

extern "C" void kernel_launch(void* const* d_in, const int* in_sizes, int n_in,
                              void* d_out, int out_size) {
    const float* values  = (const float*)d_in[0];
    const float* keys    = (const float*)d_in[1];
    const float* queries = (const float*)d_in[2];
    const float* Wv = (const float*)d_in[3];
    const float* Wk = (const float*)d_in[4];
    const float* Wq = (const float*)d_in[5];
    float* out = (float*)d_out;

    __nv_bfloat16 *xa, *wka, *wqb, *mb, *wvb, *ta, *ka, *va, *pa;
    float *mpart, *sc;
    cudaGetSymbolAddress((void**)&xa, g_xa);
    cudaGetSymbolAddress((void**)&wka, g_wka);
    cudaGetSymbolAddress((void**)&wqb, g_wqb);
    cudaGetSymbolAddress((void**)&mb, g_mb);
    cudaGetSymbolAddress((void**)&wvb, g_wvb);
    cudaGetSymbolAddress((void**)&ta, g_ta);
    cudaGetSymbolAddress((void**)&ka, g_ka);
    cudaGetSymbolAddress((void**)&va, g_va);
    cudaGetSymbolAddress((void**)&pa, g_pa);
    cudaGetSymbolAddress((void**)&mpart, g_mpart);
    cudaGetSymbolAddress((void**)&sc, g_s);

    const int SM_A = (128 + 128) * ROWB * 6;   // 221184 for <*,4,4,6>
    const int SM_B = (64 + 128) * ROWB * 6;    // 165888 for <*,2,4,6>
    cudaFuncSetAttribute(gemm_bf16<0, 4, 4, 6>, cudaFuncAttributeMaxDynamicSharedMemorySize, SM_A);
    cudaFuncSetAttribute(gemm_bf16<1, 2, 4, 6>, cudaFuncAttributeMaxDynamicSharedMemorySize, SM_B);
    cudaFuncSetAttribute(gemm_bf16<0, 2, 4, 6>, cudaFuncAttributeMaxDynamicSharedMemorySize, SM_B);

    // M' = Wk @ Wq^T  (split-K=4 -> partials -> B-aug)
    split_aug<true, false><<<2048, 256>>>(Wk, wka, 1024, 1024, 0, 0);
    split_aug<false, false><<<2048, 256>>>(Wq, wqb, 1024, 1024, 0, 0);
    gemm_bf16<0, 4, 4, 6><<<dim3(8, 8, 4), 256, SM_A>>>(wka, wqb, mpart, nullptr,
                                                        1024, 3072, 12, 768, 768, 1 << 20);
    reduce4_bsplit<<<2048, 256>>>(mpart, mb);

    // t = x_q @ M'^T  -> A-aug
    split_aug<true, false><<<16384, 256>>>(queries, xa, 8192, 1024, 0, 0);
    gemm_bf16<1, 2, 4, 6><<<dim3(8, 128, 1), 256, SM_B>>>(xa, mb, nullptr, ta,
                                                          1024, 3072, 48, 0, 0, 0);

    // scores = t @ x_k^T per batch
    split_aug<false, false><<<dim3(4096, 4), 256>>>(keys, ka, 2048, 1024,
                                                    2048LL * 1024, 2048LL * 3072);
    gemm_bf16<0, 4, 4, 6><<<dim3(16, 16, 4), 256, SM_A>>>(ta, ka, sc, nullptr,
                                                          2048, 3072, 48,
                                                          2048LL * 3072, 2048LL * 3072,
                                                          (long long)Sq * Sq);
    // softmax + /32 -> P A-aug
    softmax_aug<<<Bq * Sq, 256>>>(sc, pa);

    // u = P @ x_v per batch -> A-aug (reuse ta)
    split_aug<false, true><<<dim3(4096, 4), 256>>>(values, va, 1024, 2048,
                                                   2048LL * 1024, 1024LL * 6144);
    gemm_bf16<1, 2, 4, 6><<<dim3(8, 32, 4), 256, SM_B>>>(pa, va, nullptr, ta,
                                                         1024, 6144, 96,
                                                         2048LL * 6144, 1024LL * 6144,
                                                         2048LL * 3072);
    // out = u @ Wv
    split_aug<false, true><<<2048, 256>>>(Wv, wvb, 1024, 1024, 0, 0);
    gemm_bf16<0, 2, 4, 6><<<dim3(8, 128, 1), 256, SM_B>>>(ta, wvb, out, nullptr,
                                                          1024, 3072, 48, 0, 0, 0);

    (void)in_sizes; (void)n_in; (void)out_size;
}

// round 8
// speedup vs baseline: 1.2443x; 1.2443x over previous
#include <cuda_runtime.h>
#include <cuda_bf16.h>
#include <math.h>
#include <stdint.h>

#define Bq 4
#define Sq 2048
#define Eq 1024
#define ROWB 144                         // 64 bf16 = 128B data + 16B pad
#define STAGE_B ((128 + 256) * ROWB)     // 55296
#define SMEM_T (4 * STAGE_B)             // 221184

// ---------------- scratch ----------------
__device__ __align__(256) __nv_bfloat16 g_xa[8192LL * 3072];      // x_q A-aug
__device__ __align__(256) __nv_bfloat16 g_wka[1024LL * 3072];     // Wk A-aug
__device__ __align__(256) __nv_bfloat16 g_wqb[1024LL * 3072];     // Wq B-aug
__device__ __align__(256) __nv_bfloat16 g_mb[1024LL * 3072];      // M' B-aug
__device__ __align__(256) __nv_bfloat16 g_wvb[1024LL * 3072];     // Wv^T B-aug
__device__ float g_mpart[4LL * 1024 * 1024];                      // M' split-K partials
__device__ __align__(256) __nv_bfloat16 g_ta[8192LL * 3072];      // t A-aug, then u A-aug
__device__ __align__(256) __nv_bfloat16 g_ka[4LL * 2048 * 3072];  // keys B-aug per batch
__device__ __align__(256) __nv_bfloat16 g_va[4LL * 1024 * 6144];  // values^T B-aug per batch
__device__ __align__(256) __nv_bfloat16 g_pa[8192LL * 6144];      // P A-aug
__device__ float g_s[(size_t)Bq * Sq * Sq];                       // fp32 logits

// ---------------- helpers ----------------
__device__ __forceinline__ uint32_t smem_u32(const void* p) {
    uint32_t a;
    asm("{ .reg .u64 t; cvta.to.shared.u64 t, %1; cvt.u32.u64 %0, t; }" : "=r"(a) : "l"(p));
    return a;
}
__device__ __forceinline__ void cpasync16(uint32_t dst, const void* src) {
    asm volatile("cp.async.cg.shared.global [%0], [%1], 16;" :: "r"(dst), "l"(src));
}
__device__ __forceinline__ void split2(float v, __nv_bfloat16& h, __nv_bfloat16& l) {
    h = __float2bfloat16(v);
    l = __float2bfloat16(v - __bfloat162float(h));
}
__device__ __forceinline__ void mma16816(float* d, const uint32_t* a, const uint32_t* b) {
    asm volatile(
        "mma.sync.aligned.m16n8k16.row.col.f32.bf16.bf16.f32 "
        "{%0,%1,%2,%3}, {%4,%5,%6,%7}, {%8,%9}, {%0,%1,%2,%3};"
        : "+f"(d[0]), "+f"(d[1]), "+f"(d[2]), "+f"(d[3])
        : "r"(a[0]), "r"(a[1]), "r"(a[2]), "r"(a[3]), "r"(b[0]), "r"(b[1]));
}
__device__ __forceinline__ void ldsm4(uint32_t* r, uint32_t a) {
    asm volatile("ldmatrix.sync.aligned.m8n8.x4.shared.b16 {%0,%1,%2,%3}, [%4];"
                 : "=r"(r[0]), "=r"(r[1]), "=r"(r[2]), "=r"(r[3]) : "r"(a));
}

// ---------------- split fp32 -> augmented bf16 (row-major [R, 3K]) ----------------
// A-pattern {k,K+k,2K+k}={hi,hi,lo}; B-pattern {hi,lo,hi}. TRANS: dst[r][k]=src[k][r].
template <bool APAT, bool TRANS>
__global__ __launch_bounds__(256) void split_aug(const float* __restrict__ src,
                                                 __nv_bfloat16* __restrict__ dst,
                                                 int Rout, int K, long long sZ, long long dZ) {
    src += blockIdx.y * sZ;
    dst += blockIdx.y * dZ;
    long long idx = (long long)blockIdx.x * 256 + threadIdx.x;
    int row, kp;
    float v0, v1;
    if (TRANS) {
        row = (int)(idx % Rout);
        kp = (int)(idx / Rout) * 2;
        v0 = src[(long long)kp * Rout + row];
        v1 = src[(long long)(kp + 1) * Rout + row];
    } else {
        const int hk = K >> 1;
        row = (int)(idx / hk);
        kp = (int)(idx % hk) * 2;
        v0 = src[(long long)row * K + kp];
        v1 = src[(long long)row * K + kp + 1];
    }
    __nv_bfloat16 h0, l0, h1, l1;
    split2(v0, h0, l0);
    split2(v1, h1, l1);
    __nv_bfloat162 H, L;
    H.x = h0; H.y = h1;
    L.x = l0; L.y = l1;
    __nv_bfloat162* d = (__nv_bfloat162*)(dst + (long long)row * 3 * K);
    d[kp >> 1] = H;
    d[(K + kp) >> 1] = APAT ? H : L;
    d[(2 * K + kp) >> 1] = APAT ? L : H;
}

// ---------------- reduce 4 split-K partials -> B-aug (hi,lo,hi), M'[1024,1024] ----------------
__global__ __launch_bounds__(256) void reduce4_bsplit(const float* __restrict__ p,
                                                      __nv_bfloat16* __restrict__ d) {
    int i = blockIdx.x * 256 + threadIdx.x;
    int e2 = i >> 9;
    int e1 = (i & 511) * 2;
    long long o = (long long)e2 * 1024 + e1;
    float v0 = p[o] + p[o + (1 << 20)] + p[o + (2 << 20)] + p[o + (3 << 20)];
    float v1 = p[o + 1] + p[o + 1 + (1 << 20)] + p[o + 1 + (2 << 20)] + p[o + 1 + (3 << 20)];
    __nv_bfloat16 h0, l0, h1, l1;
    split2(v0, h0, l0);
    split2(v1, h1, l1);
    __nv_bfloat162 H, L;
    H.x = h0; H.y = h1;
    L.x = l0; L.y = l1;
    __nv_bfloat162* q = (__nv_bfloat162*)(d + (long long)e2 * 3072);
    q[e1 >> 1] = H;
    q[(1024 + e1) >> 1] = L;
    q[(2048 + e1) >> 1] = H;
}

// ---------------- pipelined bf16 mma.sync GEMM, CTA 128x256, warp 64x64, 1-sync loop ----------------
// EPI 0: f32 C (+z*cZ). EPI 1: A-aug (hi,hi,lo) at aux(+z*cZ)[row*3072 + {n,1024+n,2048+n}]
template <int EPI>
__global__ __launch_bounds__(256, 1)
void gemm_bf16(const __nv_bfloat16* __restrict__ A, const __nv_bfloat16* __restrict__ B,
               float* __restrict__ Cf, __nv_bfloat16* __restrict__ aux,
               int N, int Kp, int kiters, long long aZ, long long bZ, long long cZ) {
    extern __shared__ char smem[];
    const uint32_t sb = smem_u32(smem);
    const int tid = threadIdx.x;
    const int lane = tid & 31, g = lane >> 2, c = lane & 3;
    const int wid = tid >> 5, wm = wid & 1, wn = wid >> 1;

    const char* Ab = (const char*)(A + blockIdx.z * aZ + (long long)(blockIdx.y * 128) * Kp);
    const char* Bb = (const char*)(B + blockIdx.z * bZ + (long long)(blockIdx.x * 256) * Kp);
    const long long rowbytes = (long long)Kp * 2;

    uint32_t aOff[4], bOff[4];
#pragma unroll
    for (int i = 0; i < 4; i++)
        aOff[i] = (wm * 64 + i * 16 + (lane & 7) + 8 * ((lane >> 3) & 1)) * ROWB + 16 * ((lane >> 4) & 1);
#pragma unroll
    for (int jp = 0; jp < 4; jp++)
        bOff[jp] = (128 + wn * 64 + jp * 16 + (lane & 7) + 8 * ((lane >> 4) & 1)) * ROWB + 16 * ((lane >> 3) & 1);

    auto load_stage = [&](int s, int ck, bool active) {
        if (active) {
            uint32_t d0 = sb + s * STAGE_B;
            long long off = (long long)ck * 128;
#pragma unroll
            for (int t = 0; t < 4; t++) {
                int idx = tid + 256 * t, r = idx >> 3, sg = (idx & 7) * 16;
                cpasync16(d0 + r * ROWB + sg, Ab + (long long)r * rowbytes + off + sg);
            }
#pragma unroll
            for (int t = 4; t < 12; t++) {
                int idx = tid + 256 * t, r = idx >> 3, sg = (idx & 7) * 16;
                cpasync16(d0 + r * ROWB + sg, Bb + (long long)(r - 128) * rowbytes + off + sg);
            }
        }
        asm volatile("cp.async.commit_group;");
    };

    float acc[4][8][4];
#pragma unroll
    for (int i = 0; i < 4; i++)
#pragma unroll
        for (int j = 0; j < 8; j++)
#pragma unroll
            for (int r = 0; r < 4; r++) acc[i][j][r] = 0.0f;

#pragma unroll
    for (int s = 0; s < 3; s++) load_stage(s, s, s < kiters);

    for (int k = 0; k < kiters; k++) {
        asm volatile("cp.async.wait_group 2;");
        __syncthreads();
        const int nk = k + 3;
        load_stage(nk & 3, nk, nk < kiters);          // overlaps with MMAs below
        const uint32_t sk = sb + (k & 3) * STAGE_B;
#pragma unroll
        for (int ks = 0; ks < 4; ks++) {
            uint32_t af[4][4], bfr[8][2];
#pragma unroll
            for (int i = 0; i < 4; i++) ldsm4(af[i], sk + aOff[i] + ks * 32);
#pragma unroll
            for (int jp = 0; jp < 4; jp++) {
                uint32_t q[4];
                ldsm4(q, sk + bOff[jp] + ks * 32);
                bfr[2 * jp][0] = q[0];
                bfr[2 * jp][1] = q[1];
                bfr[2 * jp + 1][0] = q[2];
                bfr[2 * jp + 1][1] = q[3];
            }
#pragma unroll
            for (int i = 0; i < 4; i++)
#pragma unroll
                for (int j = 0; j < 8; j++) mma16816(acc[i][j], af[i], bfr[j]);
        }
    }

#pragma unroll
    for (int i = 0; i < 4; i++) {
#pragma unroll
        for (int j = 0; j < 8; j++) {
            const int r0 = blockIdx.y * 128 + wm * 64 + i * 16 + g;
            const int n0 = blockIdx.x * 256 + wn * 64 + j * 8 + 2 * c;
            if (EPI == 0) {
                float* Cb = Cf + blockIdx.z * cZ;
                float2 lo, hi;
                lo.x = acc[i][j][0]; lo.y = acc[i][j][1];
                hi.x = acc[i][j][2]; hi.y = acc[i][j][3];
                *(float2*)&Cb[(long long)r0 * N + n0] = lo;
                *(float2*)&Cb[(long long)(r0 + 8) * N + n0] = hi;
            } else {
                __nv_bfloat16* ab = aux + blockIdx.z * cZ;
#pragma unroll
                for (int rr = 0; rr < 2; rr++) {
                    const int row = r0 + 8 * rr;
                    __nv_bfloat16 h0, l0, h1, l1;
                    split2(acc[i][j][2 * rr], h0, l0);
                    split2(acc[i][j][2 * rr + 1], h1, l1);
                    __nv_bfloat162 H, L;
                    H.x = h0; H.y = h1;
                    L.x = l0; L.y = l1;
                    __nv_bfloat162* p2 = (__nv_bfloat162*)(ab + (long long)row * 3072);
                    p2[n0 >> 1] = H;
                    p2[(1024 + n0) >> 1] = H;
                    p2[(2048 + n0) >> 1] = L;
                }
            }
        }
    }
}

// ---------------- softmax + /32 -> P A-aug [row, 6144] ----------------
__global__ __launch_bounds__(256) void softmax_aug(const float* __restrict__ S,
                                                   __nv_bfloat16* __restrict__ pa) {
    const float* row = S + (long long)blockIdx.x * Sq;
    __nv_bfloat16* d = pa + (long long)blockIdx.x * 6144;
    const int tid = threadIdx.x;
    float vals[8], m = -INFINITY;
#pragma unroll
    for (int i = 0; i < 8; i++) { vals[i] = row[tid + i * 256]; m = fmaxf(m, vals[i]); }
    __shared__ float red[256];
    red[tid] = m;
    __syncthreads();
    for (int s = 128; s > 0; s >>= 1) { if (tid < s) red[tid] = fmaxf(red[tid], red[tid + s]); __syncthreads(); }
    m = red[0];
    __syncthreads();
    float sum = 0.f;
#pragma unroll
    for (int i = 0; i < 8; i++) { vals[i] = expf(vals[i] - m); sum += vals[i]; }
    red[tid] = sum;
    __syncthreads();
    for (int s = 128; s > 0; s >>= 1) { if (tid < s) red[tid] += red[tid + s]; __syncthreads(); }
    const float inv = 1.0f / (red[0] * 32.0f);
#pragma unroll
    for (int i = 0; i < 8; i++) {
        const int j = tid + i * 256;
        __nv_bfloat16 h, l;
        split2(vals[i] * inv, h, l);
        d[j] = h;
        d[2048 + j] = h;
        d[4096 + j] = l;
    }
}

extern "C" void kernel_launch(void* const* d_in, const int* in_sizes, int n_in,
                              void* d_out, int out_size) {
    const float* values  = (const float*)d_in[0];
    const float* keys    = (const float*)d_in[1];
    const float* queries = (const float*)d_in[2];
    const float* Wv = (const float*)d_in[3];
    const float* Wk = (const float*)d_in[4];
    const float* Wq = (const float*)d_in[5];
    float* out = (float*)d_out;

    __nv_bfloat16 *xa, *wka, *wqb, *mb, *wvb, *ta, *ka, *va, *pa;
    float *mpart, *sc;
    cudaGetSymbolAddress((void**)&xa, g_xa);
    cudaGetSymbolAddress((void**)&wka, g_wka);
    cudaGetSymbolAddress((void**)&wqb, g_wqb);
    cudaGetSymbolAddress((void**)&mb, g_mb);
    cudaGetSymbolAddress((void**)&wvb, g_wvb);
    cudaGetSymbolAddress((void**)&ta, g_ta);
    cudaGetSymbolAddress((void**)&ka, g_ka);
    cudaGetSymbolAddress((void**)&va, g_va);
    cudaGetSymbolAddress((void**)&pa, g_pa);
    cudaGetSymbolAddress((void**)&mpart, g_mpart);
    cudaGetSymbolAddress((void**)&sc, g_s);

    cudaFuncSetAttribute(gemm_bf16<0>, cudaFuncAttributeMaxDynamicSharedMemorySize, SMEM_T);
    cudaFuncSetAttribute(gemm_bf16<1>, cudaFuncAttributeMaxDynamicSharedMemorySize, SMEM_T);

    // M'[b,a] = Wk @ Wq^T  (split-K=4 over K'=3072)
    split_aug<true, false><<<2048, 256>>>(Wk, wka, 1024, 1024, 0, 0);
    split_aug<false, false><<<2048, 256>>>(Wq, wqb, 1024, 1024, 0, 0);
    gemm_bf16<0><<<dim3(4, 8, 4), 256, SMEM_T>>>(wka, wqb, mpart, nullptr,
                                                 1024, 3072, 12, 768, 768, 1 << 20);
    reduce4_bsplit<<<2048, 256>>>(mpart, mb);

    // t = x_q @ M'^T -> A-aug
    split_aug<true, false><<<16384, 256>>>(queries, xa, 8192, 1024, 0, 0);
    gemm_bf16<1><<<dim3(4, 64, 1), 256, SMEM_T>>>(xa, mb, nullptr, ta, 1024, 3072, 48, 0, 0, 0);

    // scores = t @ x_k^T per batch
    split_aug<false, false><<<dim3(4096, 4), 256>>>(keys, ka, 2048, 1024,
                                                    2048LL * 1024, 2048LL * 3072);
    gemm_bf16<0><<<dim3(8, 16, 4), 256, SMEM_T>>>(ta, ka, sc, nullptr, 2048, 3072, 48,
                                                  2048LL * 3072, 2048LL * 3072, (long long)Sq * Sq);
    // softmax + /32 -> P A-aug
    softmax_aug<<<Bq * Sq, 256>>>(sc, pa);

    // u = P @ x_v per batch -> A-aug (reuse ta)
    split_aug<false, true><<<dim3(4096, 4), 256>>>(values, va, 1024, 2048,
                                                   2048LL * 1024, 1024LL * 6144);
    gemm_bf16<1><<<dim3(4, 16, 4), 256, SMEM_T>>>(pa, va, nullptr, ta, 1024, 6144, 96,
                                                  2048LL * 6144, 1024LL * 6144, 2048LL * 3072);
    // out = u @ Wv
    split_aug<false, true><<<2048, 256>>>(Wv, wvb, 1024, 1024, 0, 0);
    gemm_bf16<0><<<dim3(4, 64, 1), 256, SMEM_T>>>(ta, wvb, out, nullptr, 1024, 3072, 48, 0, 0, 0);

    (void)in_sizes; (void)n_in; (void)out_size;
}

// round 9
// speedup vs baseline: 1.4875x; 1.1954x over previous
#include <cuda_runtime.h>
#include <cuda_bf16.h>
#include <cuda_fp16.h>
#include <math.h>
#include <stdint.h>

#define Bq 4
#define Sq 2048
#define Eq 1024
#define ROWB 144
#define STAGE_B ((128 + 256) * ROWB)
#define SMEM_T (4 * STAGE_B)

// ---------------- scratch ----------------
__device__ __align__(256) __nv_bfloat16 g_xa[8192LL * 3072];      // x_q A-aug bf16
__device__ __align__(256) __nv_bfloat16 g_wka[1024LL * 3072];     // Wk A-aug
__device__ __align__(256) __nv_bfloat16 g_wqb[1024LL * 3072];     // Wq B-aug
__device__ __align__(256) __nv_bfloat16 g_mb[1024LL * 3072];      // M' B-aug
__device__ __align__(256) __half g_wvh[1024LL * 1024];            // Wv^T fp16
__device__ float g_mpart[4LL * 1024 * 1024];                      // M' split-K partials
__device__ __align__(256) __nv_bfloat16 g_ta[8192LL * 3072];      // t A-aug; later u fp16-aug (32MB)
__device__ __align__(256) __nv_bfloat16 g_ka[4LL * 2048 * 3072];  // keys B-aug per batch
__device__ __align__(256) __half g_va[4LL * 1024 * 2048];         // values^T fp16 per batch
__device__ __align__(256) __half g_pa[8192LL * 4096];             // P fp16 [ph|pl]
__device__ float g_s[(size_t)Bq * Sq * Sq];                       // fp32 logits

// ---------------- helpers ----------------
__device__ __forceinline__ uint32_t smem_u32(const void* p) {
    uint32_t a;
    asm("{ .reg .u64 t; cvta.to.shared.u64 t, %1; cvt.u32.u64 %0, t; }" : "=r"(a) : "l"(p));
    return a;
}
__device__ __forceinline__ void cpasync16(uint32_t dst, const void* src) {
    asm volatile("cp.async.cg.shared.global [%0], [%1], 16;" :: "r"(dst), "l"(src));
}
__device__ __forceinline__ void split2(float v, __nv_bfloat16& h, __nv_bfloat16& l) {
    h = __float2bfloat16(v);
    l = __float2bfloat16(v - __bfloat162float(h));
}
__device__ __forceinline__ void split2h(float v, __half& h, __half& l) {
    h = __float2half(v);
    l = __float2half(v - __half2float(h));
}
__device__ __forceinline__ void mma_bf16(float* d, const uint32_t* a, const uint32_t* b) {
    asm volatile(
        "mma.sync.aligned.m16n8k16.row.col.f32.bf16.bf16.f32 "
        "{%0,%1,%2,%3}, {%4,%5,%6,%7}, {%8,%9}, {%0,%1,%2,%3};"
        : "+f"(d[0]), "+f"(d[1]), "+f"(d[2]), "+f"(d[3])
        : "r"(a[0]), "r"(a[1]), "r"(a[2]), "r"(a[3]), "r"(b[0]), "r"(b[1]));
}
__device__ __forceinline__ void mma_f16(float* d, const uint32_t* a, const uint32_t* b) {
    asm volatile(
        "mma.sync.aligned.m16n8k16.row.col.f32.f16.f16.f32 "
        "{%0,%1,%2,%3}, {%4,%5,%6,%7}, {%8,%9}, {%0,%1,%2,%3};"
        : "+f"(d[0]), "+f"(d[1]), "+f"(d[2]), "+f"(d[3])
        : "r"(a[0]), "r"(a[1]), "r"(a[2]), "r"(a[3]), "r"(b[0]), "r"(b[1]));
}
__device__ __forceinline__ void ldsm4(uint32_t* r, uint32_t a) {
    asm volatile("ldmatrix.sync.aligned.m8n8.x4.shared.b16 {%0,%1,%2,%3}, [%4];"
                 : "=r"(r[0]), "=r"(r[1]), "=r"(r[2]), "=r"(r[3]) : "r"(a));
}

// ---------------- split fp32 -> augmented bf16 [R, 3K] ----------------
template <bool APAT, bool TRANS>
__global__ __launch_bounds__(256) void split_aug(const float* __restrict__ src,
                                                 __nv_bfloat16* __restrict__ dst,
                                                 int Rout, int K, long long sZ, long long dZ) {
    src += blockIdx.y * sZ;
    dst += blockIdx.y * dZ;
    long long idx = (long long)blockIdx.x * 256 + threadIdx.x;
    int row, kp;
    float v0, v1;
    if (TRANS) {
        row = (int)(idx % Rout);
        kp = (int)(idx / Rout) * 2;
        v0 = src[(long long)kp * Rout + row];
        v1 = src[(long long)(kp + 1) * Rout + row];
    } else {
        const int hk = K >> 1;
        row = (int)(idx / hk);
        kp = (int)(idx % hk) * 2;
        v0 = src[(long long)row * K + kp];
        v1 = src[(long long)row * K + kp + 1];
    }
    __nv_bfloat16 h0, l0, h1, l1;
    split2(v0, h0, l0);
    split2(v1, h1, l1);
    __nv_bfloat162 H, L;
    H.x = h0; H.y = h1;
    L.x = l0; L.y = l1;
    __nv_bfloat162* d = (__nv_bfloat162*)(dst + (long long)row * 3 * K);
    d[kp >> 1] = H;
    d[(K + kp) >> 1] = APAT ? H : L;
    d[(2 * K + kp) >> 1] = APAT ? L : H;
}

// ---------------- transpose+convert fp32 -> fp16 [Rout, K] (dst[r][k]=src[k][r]) ----------------
__global__ __launch_bounds__(256) void split_h_trans(const float* __restrict__ src,
                                                     __half* __restrict__ dst,
                                                     int Rout, int K, long long sZ, long long dZ) {
    src += blockIdx.y * sZ;
    dst += blockIdx.y * dZ;
    long long idx = (long long)blockIdx.x * 256 + threadIdx.x;
    int row = (int)(idx % Rout);
    int kp = (int)(idx / Rout) * 2;
    float v0 = src[(long long)kp * Rout + row];
    float v1 = src[(long long)(kp + 1) * Rout + row];
    __half2 H;
    H.x = __float2half(v0);
    H.y = __float2half(v1);
    *(__half2*)(dst + (long long)row * K + kp) = H;
}

// ---------------- reduce 4 split-K partials -> B-aug (hi,lo,hi) ----------------
__global__ __launch_bounds__(256) void reduce4_bsplit(const float* __restrict__ p,
                                                      __nv_bfloat16* __restrict__ d) {
    int i = blockIdx.x * 256 + threadIdx.x;
    int e2 = i >> 9;
    int e1 = (i & 511) * 2;
    long long o = (long long)e2 * 1024 + e1;
    float v0 = p[o] + p[o + (1 << 20)] + p[o + (2 << 20)] + p[o + (3 << 20)];
    float v1 = p[o + 1] + p[o + 1 + (1 << 20)] + p[o + 1 + (2 << 20)] + p[o + 1 + (3 << 20)];
    __nv_bfloat16 h0, l0, h1, l1;
    split2(v0, h0, l0);
    split2(v1, h1, l1);
    __nv_bfloat162 H, L;
    H.x = h0; H.y = h1;
    L.x = l0; L.y = l1;
    __nv_bfloat162* q = (__nv_bfloat162*)(d + (long long)e2 * 3072);
    q[e1 >> 1] = H;
    q[(1024 + e1) >> 1] = L;
    q[(2048 + e1) >> 1] = H;
}

// ---------------- pipelined mma.sync GEMM, CTA 128x256, warp 64x64 ----------------
// FT: 0 bf16 mma, 1 fp16 mma. B chunk index wraps at bmod (enables [hi|hi] reuse).
// EPI 0: f32*cscale; EPI 1: bf16 A-aug (hi,hi,lo) stride 3072; EPI 2: fp16 A-aug (hi,lo) stride 2048.
template <int EPI, int FT>
__global__ __launch_bounds__(256, 1)
void gemm_mma(const __nv_bfloat16* __restrict__ A, const __nv_bfloat16* __restrict__ B,
              float* __restrict__ Cf, void* __restrict__ aux,
              int N, int Kp, int bKp, int kiters, int bmod, float cscale,
              long long aZ, long long bZ, long long cZ) {
    extern __shared__ char smem[];
    const uint32_t sb = smem_u32(smem);
    const int tid = threadIdx.x;
    const int lane = tid & 31, g = lane >> 2, c = lane & 3;
    const int wid = tid >> 5, wm = wid & 1, wn = wid >> 1;

    const char* Ab = (const char*)(A + blockIdx.z * aZ + (long long)(blockIdx.y * 128) * Kp);
    const char* Bb = (const char*)(B + blockIdx.z * bZ + (long long)(blockIdx.x * 256) * bKp);
    const long long arows = (long long)Kp * 2, brows = (long long)bKp * 2;

    uint32_t aOff[4], bOff[4];
#pragma unroll
    for (int i = 0; i < 4; i++)
        aOff[i] = (wm * 64 + i * 16 + (lane & 7) + 8 * ((lane >> 3) & 1)) * ROWB + 16 * ((lane >> 4) & 1);
#pragma unroll
    for (int jp = 0; jp < 4; jp++)
        bOff[jp] = (128 + wn * 64 + jp * 16 + (lane & 7) + 8 * ((lane >> 4) & 1)) * ROWB + 16 * ((lane >> 3) & 1);

    auto load_stage = [&](int s, int ck, bool active) {
        if (active) {
            uint32_t d0 = sb + s * STAGE_B;
            long long offA = (long long)ck * 128;
            long long offB = (long long)(ck % bmod) * 128;
#pragma unroll
            for (int t = 0; t < 4; t++) {
                int idx = tid + 256 * t, r = idx >> 3, sg = (idx & 7) * 16;
                cpasync16(d0 + r * ROWB + sg, Ab + (long long)r * arows + offA + sg);
            }
#pragma unroll
            for (int t = 4; t < 12; t++) {
                int idx = tid + 256 * t, r = idx >> 3, sg = (idx & 7) * 16;
                cpasync16(d0 + r * ROWB + sg, Bb + (long long)(r - 128) * brows + offB + sg);
            }
        }
        asm volatile("cp.async.commit_group;");
    };

    float acc[4][8][4];
#pragma unroll
    for (int i = 0; i < 4; i++)
#pragma unroll
        for (int j = 0; j < 8; j++)
#pragma unroll
            for (int r = 0; r < 4; r++) acc[i][j][r] = 0.0f;

#pragma unroll
    for (int s = 0; s < 3; s++) load_stage(s, s, s < kiters);

    for (int k = 0; k < kiters; k++) {
        asm volatile("cp.async.wait_group 2;");
        __syncthreads();
        const int nk = k + 3;
        load_stage(nk & 3, nk, nk < kiters);
        const uint32_t sk = sb + (k & 3) * STAGE_B;
#pragma unroll
        for (int ks = 0; ks < 4; ks++) {
            uint32_t af[4][4], bfr[8][2];
#pragma unroll
            for (int i = 0; i < 4; i++) ldsm4(af[i], sk + aOff[i] + ks * 32);
#pragma unroll
            for (int jp = 0; jp < 4; jp++) {
                uint32_t q[4];
                ldsm4(q, sk + bOff[jp] + ks * 32);
                bfr[2 * jp][0] = q[0];
                bfr[2 * jp][1] = q[1];
                bfr[2 * jp + 1][0] = q[2];
                bfr[2 * jp + 1][1] = q[3];
            }
#pragma unroll
            for (int i = 0; i < 4; i++)
#pragma unroll
                for (int j = 0; j < 8; j++) {
                    if (FT) mma_f16(acc[i][j], af[i], bfr[j]);
                    else mma_bf16(acc[i][j], af[i], bfr[j]);
                }
        }
    }

#pragma unroll
    for (int i = 0; i < 4; i++) {
#pragma unroll
        for (int j = 0; j < 8; j++) {
            const int r0 = blockIdx.y * 128 + wm * 64 + i * 16 + g;
            const int n0 = blockIdx.x * 256 + wn * 64 + j * 8 + 2 * c;
            if (EPI == 0) {
                float* Cb = Cf + blockIdx.z * cZ;
                float2 lo, hi;
                lo.x = acc[i][j][0] * cscale; lo.y = acc[i][j][1] * cscale;
                hi.x = acc[i][j][2] * cscale; hi.y = acc[i][j][3] * cscale;
                *(float2*)&Cb[(long long)r0 * N + n0] = lo;
                *(float2*)&Cb[(long long)(r0 + 8) * N + n0] = hi;
            } else if (EPI == 1) {
                __nv_bfloat16* ab = (__nv_bfloat16*)aux + blockIdx.z * cZ;
#pragma unroll
                for (int rr = 0; rr < 2; rr++) {
                    const int row = r0 + 8 * rr;
                    __nv_bfloat16 h0, l0, h1, l1;
                    split2(acc[i][j][2 * rr], h0, l0);
                    split2(acc[i][j][2 * rr + 1], h1, l1);
                    __nv_bfloat162 H, L;
                    H.x = h0; H.y = h1;
                    L.x = l0; L.y = l1;
                    __nv_bfloat162* p2 = (__nv_bfloat162*)(ab + (long long)row * 3072);
                    p2[n0 >> 1] = H;
                    p2[(1024 + n0) >> 1] = H;
                    p2[(2048 + n0) >> 1] = L;
                }
            } else {
                __half* ab = (__half*)aux + blockIdx.z * cZ;
#pragma unroll
                for (int rr = 0; rr < 2; rr++) {
                    const int row = r0 + 8 * rr;
                    __half h0, l0, h1, l1;
                    split2h(acc[i][j][2 * rr], h0, l0);
                    split2h(acc[i][j][2 * rr + 1], h1, l1);
                    __half2 H, L;
                    H.x = h0; H.y = h1;
                    L.x = l0; L.y = l1;
                    __half2* p2 = (__half2*)(ab + (long long)row * 2048);
                    p2[n0 >> 1] = H;
                    p2[(1024 + n0) >> 1] = L;
                }
            }
        }
    }
}

// ---------------- softmax (no /32; folded into out-GEMM) -> P fp16 [ph(2048)|pl(2048)] ----------------
__global__ __launch_bounds__(256) void softmax_fp16(const float* __restrict__ S,
                                                    __half* __restrict__ pa) {
    const float* row = S + (long long)blockIdx.x * Sq;
    __half* d = pa + (long long)blockIdx.x * 4096;
    const int tid = threadIdx.x;
    float vals[8], m = -INFINITY;
#pragma unroll
    for (int i = 0; i < 4; i++) {
        float2 f = *(const float2*)&row[i * 512 + 2 * tid];
        vals[2 * i] = f.x;
        vals[2 * i + 1] = f.y;
        m = fmaxf(m, fmaxf(f.x, f.y));
    }
    __shared__ float red[256];
    red[tid] = m;
    __syncthreads();
    for (int s = 128; s > 0; s >>= 1) { if (tid < s) red[tid] = fmaxf(red[tid], red[tid + s]); __syncthreads(); }
    m = red[0];
    __syncthreads();
    float sum = 0.f;
#pragma unroll
    for (int i = 0; i < 8; i++) { vals[i] = expf(vals[i] - m); sum += vals[i]; }
    red[tid] = sum;
    __syncthreads();
    for (int s = 128; s > 0; s >>= 1) { if (tid < s) red[tid] += red[tid + s]; __syncthreads(); }
    const float inv = 1.0f / red[0];
#pragma unroll
    for (int i = 0; i < 4; i++) {
        const int j = i * 512 + 2 * tid;
        __half h0, l0, h1, l1;
        split2h(vals[2 * i] * inv, h0, l0);
        split2h(vals[2 * i + 1] * inv, h1, l1);
        __half2 H, L;
        H.x = h0; H.y = h1;
        L.x = l0; L.y = l1;
        *(__half2*)(d + j) = H;
        *(__half2*)(d + 2048 + j) = L;
    }
}

extern "C" void kernel_launch(void* const* d_in, const int* in_sizes, int n_in,
                              void* d_out, int out_size) {
    const float* values  = (const float*)d_in[0];
    const float* keys    = (const float*)d_in[1];
    const float* queries = (const float*)d_in[2];
    const float* Wv = (const float*)d_in[3];
    const float* Wk = (const float*)d_in[4];
    const float* Wq = (const float*)d_in[5];
    float* out = (float*)d_out;

    __nv_bfloat16 *xa, *wka, *wqb, *mb, *ta, *ka;
    __half *wvh, *va, *pa;
    float *mpart, *sc;
    cudaGetSymbolAddress((void**)&xa, g_xa);
    cudaGetSymbolAddress((void**)&wka, g_wka);
    cudaGetSymbolAddress((void**)&wqb, g_wqb);
    cudaGetSymbolAddress((void**)&mb, g_mb);
    cudaGetSymbolAddress((void**)&wvh, g_wvh);
    cudaGetSymbolAddress((void**)&ta, g_ta);
    cudaGetSymbolAddress((void**)&ka, g_ka);
    cudaGetSymbolAddress((void**)&va, g_va);
    cudaGetSymbolAddress((void**)&pa, g_pa);
    cudaGetSymbolAddress((void**)&mpart, g_mpart);
    cudaGetSymbolAddress((void**)&sc, g_s);

    cudaFuncSetAttribute(gemm_mma<0, 0>, cudaFuncAttributeMaxDynamicSharedMemorySize, SMEM_T);
    cudaFuncSetAttribute(gemm_mma<1, 0>, cudaFuncAttributeMaxDynamicSharedMemorySize, SMEM_T);
    cudaFuncSetAttribute(gemm_mma<2, 1>, cudaFuncAttributeMaxDynamicSharedMemorySize, SMEM_T);
    cudaFuncSetAttribute(gemm_mma<0, 1>, cudaFuncAttributeMaxDynamicSharedMemorySize, SMEM_T);

    // M' = Wk @ Wq^T (split-K=4), bf16 3-term
    split_aug<true, false><<<2048, 256>>>(Wk, wka, 1024, 1024, 0, 0);
    split_aug<false, false><<<2048, 256>>>(Wq, wqb, 1024, 1024, 0, 0);
    gemm_mma<0, 0><<<dim3(4, 8, 4), 256, SMEM_T>>>(wka, wqb, mpart, nullptr,
                                                   1024, 3072, 3072, 12, 12, 1.0f,
                                                   768, 768, 1 << 20);
    reduce4_bsplit<<<2048, 256>>>(mpart, mb);

    // t = x_q @ M'^T -> bf16 A-aug
    split_aug<true, false><<<16384, 256>>>(queries, xa, 8192, 1024, 0, 0);
    gemm_mma<1, 0><<<dim3(4, 64, 1), 256, SMEM_T>>>(xa, mb, nullptr, ta,
                                                    1024, 3072, 3072, 48, 48, 1.0f, 0, 0, 0);

    // scores = t @ x_k^T per batch, bf16 3-term
    split_aug<false, false><<<dim3(4096, 4), 256>>>(keys, ka, 2048, 1024,
                                                    2048LL * 1024, 2048LL * 3072);
    gemm_mma<0, 0><<<dim3(8, 16, 4), 256, SMEM_T>>>(ta, ka, sc, nullptr,
                                                    2048, 3072, 3072, 48, 48, 1.0f,
                                                    2048LL * 3072, 2048LL * 3072, (long long)Sq * Sq);
    // softmax -> P fp16 [ph|pl] (no /32 here)
    softmax_fp16<<<Bq * Sq, 256>>>(sc, pa);

    // u = P @ x_v^T per batch, fp16 2-term (A=[ph|pl], B=vh repeated) -> u fp16 A-aug in ta
    split_h_trans<<<dim3(4096, 4), 256>>>(values, va, 1024, 2048, 2048LL * 1024, 1024LL * 2048);
    gemm_mma<2, 1><<<dim3(4, 16, 4), 256, SMEM_T>>>((__nv_bfloat16*)pa, (__nv_bfloat16*)va,
                                                    nullptr, ta,
                                                    1024, 4096, 2048, 64, 32, 1.0f,
                                                    2048LL * 4096, 1024LL * 2048, 2048LL * 2048);
    // out = (u @ Wv) / 32, fp16 2-term (A=[uh|ul], B=Wvh repeated)
    split_h_trans<<<2048, 256>>>(Wv, wvh, 1024, 1024, 0, 0);
    gemm_mma<0, 1><<<dim3(4, 64, 1), 256, SMEM_T>>>(ta, (__nv_bfloat16*)wvh, out, nullptr,
                                                    1024, 2048, 1024, 32, 16, 1.0f / 32.0f,
                                                    0, 0, 0);

    (void)in_sizes; (void)n_in; (void)out_size;
}

// round 10
// speedup vs baseline: 1.8355x; 1.2339x over previous
#include <cuda_runtime.h>
#include <cuda_bf16.h>
#include <cuda_fp16.h>
#include <math.h>
#include <stdint.h>

#define Bq 4
#define Sq 2048
#define Eq 1024
#define ROWB 144
#define STAGE_B ((128 + 256) * ROWB)
#define SMEM_T (4 * STAGE_B)

// ---------------- scratch ----------------
__device__ __align__(256) __nv_bfloat16 g_xa[8192LL * 3072];      // x_q A-aug bf16
__device__ __align__(256) __nv_bfloat16 g_wka[1024LL * 3072];     // Wk A-aug
__device__ __align__(256) __nv_bfloat16 g_wqb[1024LL * 3072];     // Wq B-aug
__device__ __align__(256) __nv_bfloat16 g_mb[1024LL * 3072];      // M' B-aug
__device__ __align__(256) __half g_wvh[1024LL * 1024];            // Wv^T fp16
__device__ float g_mpart[4LL * 1024 * 1024];                      // M' split-K partials
__device__ __align__(256) __nv_bfloat16 g_ta[8192LL * 3072];      // t A-aug; later u fp16
__device__ __align__(256) __nv_bfloat16 g_ka[4LL * 2048 * 3072];  // keys B-aug per batch
__device__ __align__(256) __half g_va[4LL * 1024 * 2048];         // values^T fp16 per batch
__device__ __align__(256) __half g_pa[8192LL * 2048];             // P fp16 (hi only)
__device__ float g_s[(size_t)Bq * Sq * Sq];                       // fp32 logits

// ---------------- helpers ----------------
__device__ __forceinline__ uint32_t smem_u32(const void* p) {
    uint32_t a;
    asm("{ .reg .u64 t; cvta.to.shared.u64 t, %1; cvt.u32.u64 %0, t; }" : "=r"(a) : "l"(p));
    return a;
}
__device__ __forceinline__ void cpasync16(uint32_t dst, const void* src) {
    asm volatile("cp.async.cg.shared.global [%0], [%1], 16;" :: "r"(dst), "l"(src));
}
__device__ __forceinline__ void split2(float v, __nv_bfloat16& h, __nv_bfloat16& l) {
    h = __float2bfloat16(v);
    l = __float2bfloat16(v - __bfloat162float(h));
}
__device__ __forceinline__ void mma_bf16(float* d, const uint32_t* a, const uint32_t* b) {
    asm volatile(
        "mma.sync.aligned.m16n8k16.row.col.f32.bf16.bf16.f32 "
        "{%0,%1,%2,%3}, {%4,%5,%6,%7}, {%8,%9}, {%0,%1,%2,%3};"
        : "+f"(d[0]), "+f"(d[1]), "+f"(d[2]), "+f"(d[3])
        : "r"(a[0]), "r"(a[1]), "r"(a[2]), "r"(a[3]), "r"(b[0]), "r"(b[1]));
}
__device__ __forceinline__ void mma_f16(float* d, const uint32_t* a, const uint32_t* b) {
    asm volatile(
        "mma.sync.aligned.m16n8k16.row.col.f32.f16.f16.f32 "
        "{%0,%1,%2,%3}, {%4,%5,%6,%7}, {%8,%9}, {%0,%1,%2,%3};"
        : "+f"(d[0]), "+f"(d[1]), "+f"(d[2]), "+f"(d[3])
        : "r"(a[0]), "r"(a[1]), "r"(a[2]), "r"(a[3]), "r"(b[0]), "r"(b[1]));
}
__device__ __forceinline__ void ldsm4(uint32_t* r, uint32_t a) {
    asm volatile("ldmatrix.sync.aligned.m8n8.x4.shared.b16 {%0,%1,%2,%3}, [%4];"
                 : "=r"(r[0]), "=r"(r[1]), "=r"(r[2]), "=r"(r[3]) : "r"(a));
}

// ---------------- split fp32 -> augmented bf16 [R, 3K] ----------------
template <bool APAT, bool TRANS>
__global__ __launch_bounds__(256) void split_aug(const float* __restrict__ src,
                                                 __nv_bfloat16* __restrict__ dst,
                                                 int Rout, int K, long long sZ, long long dZ) {
    src += blockIdx.y * sZ;
    dst += blockIdx.y * dZ;
    long long idx = (long long)blockIdx.x * 256 + threadIdx.x;
    int row, kp;
    float v0, v1;
    if (TRANS) {
        row = (int)(idx % Rout);
        kp = (int)(idx / Rout) * 2;
        v0 = src[(long long)kp * Rout + row];
        v1 = src[(long long)(kp + 1) * Rout + row];
    } else {
        const int hk = K >> 1;
        row = (int)(idx / hk);
        kp = (int)(idx % hk) * 2;
        v0 = src[(long long)row * K + kp];
        v1 = src[(long long)row * K + kp + 1];
    }
    __nv_bfloat16 h0, l0, h1, l1;
    split2(v0, h0, l0);
    split2(v1, h1, l1);
    __nv_bfloat162 H, L;
    H.x = h0; H.y = h1;
    L.x = l0; L.y = l1;
    __nv_bfloat162* d = (__nv_bfloat162*)(dst + (long long)row * 3 * K);
    d[kp >> 1] = H;
    d[(K + kp) >> 1] = APAT ? H : L;
    d[(2 * K + kp) >> 1] = APAT ? L : H;
}

// ---------------- transpose+convert fp32 -> fp16 [Rout, K] ----------------
__global__ __launch_bounds__(256) void split_h_trans(const float* __restrict__ src,
                                                     __half* __restrict__ dst,
                                                     int Rout, int K, long long sZ, long long dZ) {
    src += blockIdx.y * sZ;
    dst += blockIdx.y * dZ;
    long long idx = (long long)blockIdx.x * 256 + threadIdx.x;
    int row = (int)(idx % Rout);
    int kp = (int)(idx / Rout) * 2;
    __half2 H;
    H.x = __float2half(src[(long long)kp * Rout + row]);
    H.y = __float2half(src[(long long)(kp + 1) * Rout + row]);
    *(__half2*)(dst + (long long)row * K + kp) = H;
}

// ---------------- reduce 4 split-K partials -> B-aug (hi,lo,hi) ----------------
__global__ __launch_bounds__(256) void reduce4_bsplit(const float* __restrict__ p,
                                                      __nv_bfloat16* __restrict__ d) {
    int i = blockIdx.x * 256 + threadIdx.x;
    int e2 = i >> 9;
    int e1 = (i & 511) * 2;
    long long o = (long long)e2 * 1024 + e1;
    float v0 = p[o] + p[o + (1 << 20)] + p[o + (2 << 20)] + p[o + (3 << 20)];
    float v1 = p[o + 1] + p[o + 1 + (1 << 20)] + p[o + 1 + (2 << 20)] + p[o + 1 + (3 << 20)];
    __nv_bfloat16 h0, l0, h1, l1;
    split2(v0, h0, l0);
    split2(v1, h1, l1);
    __nv_bfloat162 H, L;
    H.x = h0; H.y = h1;
    L.x = l0; L.y = l1;
    __nv_bfloat162* q = (__nv_bfloat162*)(d + (long long)e2 * 3072);
    q[e1 >> 1] = H;
    q[(1024 + e1) >> 1] = L;
    q[(2048 + e1) >> 1] = H;
}

// ---------------- pipelined mma.sync GEMM, CTA 128x256, warp 64x64 ----------------
// FT: 0 bf16 mma, 1 fp16 mma.
// EPI 0: f32*cscale; EPI 1: bf16 A-aug (hi,hi,lo) stride 3072; EPI 2: fp16 hi-only, stride 1024.
template <int EPI, int FT>
__global__ __launch_bounds__(256, 1)
void gemm_mma(const __nv_bfloat16* __restrict__ A, const __nv_bfloat16* __restrict__ B,
              float* __restrict__ Cf, void* __restrict__ aux,
              int N, int Kp, int bKp, int kiters, float cscale,
              long long aZ, long long bZ, long long cZ) {
    extern __shared__ char smem[];
    const uint32_t sb = smem_u32(smem);
    const int tid = threadIdx.x;
    const int lane = tid & 31, g = lane >> 2, c = lane & 3;
    const int wid = tid >> 5, wm = wid & 1, wn = wid >> 1;

    const char* Ab = (const char*)(A + blockIdx.z * aZ + (long long)(blockIdx.y * 128) * Kp);
    const char* Bb = (const char*)(B + blockIdx.z * bZ + (long long)(blockIdx.x * 256) * bKp);
    const long long arows = (long long)Kp * 2, brows = (long long)bKp * 2;

    uint32_t aOff[4], bOff[4];
#pragma unroll
    for (int i = 0; i < 4; i++)
        aOff[i] = (wm * 64 + i * 16 + (lane & 7) + 8 * ((lane >> 3) & 1)) * ROWB + 16 * ((lane >> 4) & 1);
#pragma unroll
    for (int jp = 0; jp < 4; jp++)
        bOff[jp] = (128 + wn * 64 + jp * 16 + (lane & 7) + 8 * ((lane >> 4) & 1)) * ROWB + 16 * ((lane >> 3) & 1);

    auto load_stage = [&](int s, int ck, bool active) {
        if (active) {
            uint32_t d0 = sb + s * STAGE_B;
            long long offA = (long long)ck * 128;
            long long offB = (long long)ck * 128;
#pragma unroll
            for (int t = 0; t < 4; t++) {
                int idx = tid + 256 * t, r = idx >> 3, sg = (idx & 7) * 16;
                cpasync16(d0 + r * ROWB + sg, Ab + (long long)r * arows + offA + sg);
            }
#pragma unroll
            for (int t = 4; t < 12; t++) {
                int idx = tid + 256 * t, r = idx >> 3, sg = (idx & 7) * 16;
                cpasync16(d0 + r * ROWB + sg, Bb + (long long)(r - 128) * brows + offB + sg);
            }
        }
        asm volatile("cp.async.commit_group;");
    };

    float acc[4][8][4];
#pragma unroll
    for (int i = 0; i < 4; i++)
#pragma unroll
        for (int j = 0; j < 8; j++)
#pragma unroll
            for (int r = 0; r < 4; r++) acc[i][j][r] = 0.0f;

#pragma unroll
    for (int s = 0; s < 3; s++) load_stage(s, s, s < kiters);

    for (int k = 0; k < kiters; k++) {
        asm volatile("cp.async.wait_group 2;");
        __syncthreads();
        const int nk = k + 3;
        load_stage(nk & 3, nk, nk < kiters);
        const uint32_t sk = sb + (k & 3) * STAGE_B;
#pragma unroll
        for (int ks = 0; ks < 4; ks++) {
            uint32_t af[4][4], bfr[8][2];
#pragma unroll
            for (int i = 0; i < 4; i++) ldsm4(af[i], sk + aOff[i] + ks * 32);
#pragma unroll
            for (int jp = 0; jp < 4; jp++) {
                uint32_t q[4];
                ldsm4(q, sk + bOff[jp] + ks * 32);
                bfr[2 * jp][0] = q[0];
                bfr[2 * jp][1] = q[1];
                bfr[2 * jp + 1][0] = q[2];
                bfr[2 * jp + 1][1] = q[3];
            }
#pragma unroll
            for (int i = 0; i < 4; i++)
#pragma unroll
                for (int j = 0; j < 8; j++) {
                    if (FT) mma_f16(acc[i][j], af[i], bfr[j]);
                    else mma_bf16(acc[i][j], af[i], bfr[j]);
                }
        }
    }

#pragma unroll
    for (int i = 0; i < 4; i++) {
#pragma unroll
        for (int j = 0; j < 8; j++) {
            const int r0 = blockIdx.y * 128 + wm * 64 + i * 16 + g;
            const int n0 = blockIdx.x * 256 + wn * 64 + j * 8 + 2 * c;
            if (EPI == 0) {
                float* Cb = Cf + blockIdx.z * cZ;
                float2 lo, hi;
                lo.x = acc[i][j][0] * cscale; lo.y = acc[i][j][1] * cscale;
                hi.x = acc[i][j][2] * cscale; hi.y = acc[i][j][3] * cscale;
                *(float2*)&Cb[(long long)r0 * N + n0] = lo;
                *(float2*)&Cb[(long long)(r0 + 8) * N + n0] = hi;
            } else if (EPI == 1) {
                __nv_bfloat16* ab = (__nv_bfloat16*)aux + blockIdx.z * cZ;
#pragma unroll
                for (int rr = 0; rr < 2; rr++) {
                    const int row = r0 + 8 * rr;
                    __nv_bfloat16 h0, l0, h1, l1;
                    split2(acc[i][j][2 * rr], h0, l0);
                    split2(acc[i][j][2 * rr + 1], h1, l1);
                    __nv_bfloat162 H, L;
                    H.x = h0; H.y = h1;
                    L.x = l0; L.y = l1;
                    __nv_bfloat162* p2 = (__nv_bfloat162*)(ab + (long long)row * 3072);
                    p2[n0 >> 1] = H;
                    p2[(1024 + n0) >> 1] = H;
                    p2[(2048 + n0) >> 1] = L;
                }
            } else {
                __half* ab = (__half*)aux + blockIdx.z * cZ;
#pragma unroll
                for (int rr = 0; rr < 2; rr++) {
                    const int row = r0 + 8 * rr;
                    __half2 H;
                    H.x = __float2half(acc[i][j][2 * rr]);
                    H.y = __float2half(acc[i][j][2 * rr + 1]);
                    *(__half2*)((__half*)(ab + (long long)row * 1024) + n0) = H;
                }
            }
        }
    }
}

// ---------------- softmax (no /32) -> P fp16 hi-only [row, 2048] ----------------
__global__ __launch_bounds__(256) void softmax_fp16(const float* __restrict__ S,
                                                    __half* __restrict__ pa) {
    const float* row = S + (long long)blockIdx.x * Sq;
    __half* d = pa + (long long)blockIdx.x * 2048;
    const int tid = threadIdx.x;
    float vals[8], m = -INFINITY;
#pragma unroll
    for (int i = 0; i < 4; i++) {
        float2 f = *(const float2*)&row[i * 512 + 2 * tid];
        vals[2 * i] = f.x;
        vals[2 * i + 1] = f.y;
        m = fmaxf(m, fmaxf(f.x, f.y));
    }
    __shared__ float red[256];
    red[tid] = m;
    __syncthreads();
    for (int s = 128; s > 0; s >>= 1) { if (tid < s) red[tid] = fmaxf(red[tid], red[tid + s]); __syncthreads(); }
    m = red[0];
    __syncthreads();
    float sum = 0.f;
#pragma unroll
    for (int i = 0; i < 8; i++) { vals[i] = expf(vals[i] - m); sum += vals[i]; }
    red[tid] = sum;
    __syncthreads();
    for (int s = 128; s > 0; s >>= 1) { if (tid < s) red[tid] += red[tid + s]; __syncthreads(); }
    const float inv = 1.0f / red[0];
#pragma unroll
    for (int i = 0; i < 4; i++) {
        const int j = i * 512 + 2 * tid;
        __half2 H;
        H.x = __float2half(vals[2 * i] * inv);
        H.y = __float2half(vals[2 * i + 1] * inv);
        *(__half2*)(d + j) = H;
    }
}

extern "C" void kernel_launch(void* const* d_in, const int* in_sizes, int n_in,
                              void* d_out, int out_size) {
    const float* values  = (const float*)d_in[0];
    const float* keys    = (const float*)d_in[1];
    const float* queries = (const float*)d_in[2];
    const float* Wv = (const float*)d_in[3];
    const float* Wk = (const float*)d_in[4];
    const float* Wq = (const float*)d_in[5];
    float* out = (float*)d_out;

    __nv_bfloat16 *xa, *wka, *wqb, *mb, *ta, *ka;
    __half *wvh, *va, *pa;
    float *mpart, *sc;
    cudaGetSymbolAddress((void**)&xa, g_xa);
    cudaGetSymbolAddress((void**)&wka, g_wka);
    cudaGetSymbolAddress((void**)&wqb, g_wqb);
    cudaGetSymbolAddress((void**)&mb, g_mb);
    cudaGetSymbolAddress((void**)&wvh, g_wvh);
    cudaGetSymbolAddress((void**)&ta, g_ta);
    cudaGetSymbolAddress((void**)&ka, g_ka);
    cudaGetSymbolAddress((void**)&va, g_va);
    cudaGetSymbolAddress((void**)&pa, g_pa);
    cudaGetSymbolAddress((void**)&mpart, g_mpart);
    cudaGetSymbolAddress((void**)&sc, g_s);

    cudaFuncSetAttribute(gemm_mma<0, 0>, cudaFuncAttributeMaxDynamicSharedMemorySize, SMEM_T);
    cudaFuncSetAttribute(gemm_mma<1, 0>, cudaFuncAttributeMaxDynamicSharedMemorySize, SMEM_T);
    cudaFuncSetAttribute(gemm_mma<2, 1>, cudaFuncAttributeMaxDynamicSharedMemorySize, SMEM_T);
    cudaFuncSetAttribute(gemm_mma<0, 1>, cudaFuncAttributeMaxDynamicSharedMemorySize, SMEM_T);

    // M' = Wk @ Wq^T (split-K=4), bf16 3-term
    split_aug<true, false><<<2048, 256>>>(Wk, wka, 1024, 1024, 0, 0);
    split_aug<false, false><<<2048, 256>>>(Wq, wqb, 1024, 1024, 0, 0);
    gemm_mma<0, 0><<<dim3(4, 8, 4), 256, SMEM_T>>>(wka, wqb, mpart, nullptr,
                                                   1024, 3072, 3072, 12, 1.0f,
                                                   768, 768, 1 << 20);
    reduce4_bsplit<<<2048, 256>>>(mpart, mb);

    // t = x_q @ M'^T -> bf16 A-aug
    split_aug<true, false><<<16384, 256>>>(queries, xa, 8192, 1024, 0, 0);
    gemm_mma<1, 0><<<dim3(4, 64, 1), 256, SMEM_T>>>(xa, mb, nullptr, ta,
                                                    1024, 3072, 3072, 48, 1.0f, 0, 0, 0);

    // scores = t @ x_k^T per batch, bf16 3-term
    split_aug<false, false><<<dim3(4096, 4), 256>>>(keys, ka, 2048, 1024,
                                                    2048LL * 1024, 2048LL * 3072);
    gemm_mma<0, 0><<<dim3(8, 16, 4), 256, SMEM_T>>>(ta, ka, sc, nullptr,
                                                    2048, 3072, 3072, 48, 1.0f,
                                                    2048LL * 3072, 2048LL * 3072, (long long)Sq * Sq);
    // softmax -> P fp16 hi-only
    softmax_fp16<<<Bq * Sq, 256>>>(sc, pa);

    // u = P @ x_v^T per batch, fp16 1-term -> u fp16 in ta
    split_h_trans<<<dim3(4096, 4), 256>>>(values, va, 1024, 2048, 2048LL * 1024, 1024LL * 2048);
    gemm_mma<2, 1><<<dim3(4, 16, 4), 256, SMEM_T>>>((__nv_bfloat16*)pa, (__nv_bfloat16*)va,
                                                    nullptr, ta,
                                                    1024, 2048, 2048, 32, 1.0f,
                                                    2048LL * 2048, 1024LL * 2048, 2048LL * 1024);
    // out = (u @ Wv) / 32, fp16 1-term
    split_h_trans<<<2048, 256>>>(Wv, wvh, 1024, 1024, 0, 0);
    gemm_mma<0, 1><<<dim3(4, 64, 1), 256, SMEM_T>>>(ta, (__nv_bfloat16*)wvh, out, nullptr,
                                                    1024, 1024, 1024, 16, 1.0f / 32.0f,
                                                    0, 0, 0);

    (void)in_sizes; (void)n_in; (void)out_size;
}

// round 11
// speedup vs baseline: 1.9420x; 1.0580x over previous
#include <cuda_runtime.h>
#include <cuda_bf16.h>
#include <cuda_fp16.h>
#include <math.h>
#include <stdint.h>

#define Bq 4
#define Sq 2048
#define Eq 1024
#define ROWB 144
#define STAGE_B (256 * ROWB)      // 128 A rows + 128 B rows = 36864 B
#define SMEM_T (3 * STAGE_B)      // 110592 B -> 2 CTAs/SM

// ---------------- scratch ----------------
__device__ __align__(256) __nv_bfloat16 g_xa[8192LL * 3072];      // x_q A-aug bf16
__device__ __align__(256) __nv_bfloat16 g_wka[1024LL * 3072];     // Wk A-aug
__device__ __align__(256) __nv_bfloat16 g_wqb[1024LL * 3072];     // Wq B-aug
__device__ __align__(256) __nv_bfloat16 g_mb[1024LL * 3072];      // M' B-aug
__device__ __align__(256) __half g_wvh[1024LL * 1024];            // Wv^T fp16
__device__ float g_mpart[4LL * 1024 * 1024];                      // M' split-K partials
__device__ __align__(256) __nv_bfloat16 g_ta[8192LL * 3072];      // t A-aug; later u fp16
__device__ __align__(256) __nv_bfloat16 g_ka[4LL * 2048 * 3072];  // keys B-aug per batch
__device__ __align__(256) __half g_va[4LL * 1024 * 2048];         // values^T fp16 per batch
__device__ __align__(256) __half g_pa[8192LL * 2048];             // P fp16 (hi only)
__device__ float g_s[(size_t)Bq * Sq * Sq];                       // fp32 logits

// ---------------- helpers ----------------
__device__ __forceinline__ uint32_t smem_u32(const void* p) {
    uint32_t a;
    asm("{ .reg .u64 t; cvta.to.shared.u64 t, %1; cvt.u32.u64 %0, t; }" : "=r"(a) : "l"(p));
    return a;
}
__device__ __forceinline__ void cpasync16(uint32_t dst, const void* src) {
    asm volatile("cp.async.cg.shared.global [%0], [%1], 16;" :: "r"(dst), "l"(src));
}
__device__ __forceinline__ void split2(float v, __nv_bfloat16& h, __nv_bfloat16& l) {
    h = __float2bfloat16(v);
    l = __float2bfloat16(v - __bfloat162float(h));
}
__device__ __forceinline__ void mma_bf16(float* d, const uint32_t* a, const uint32_t* b) {
    asm volatile(
        "mma.sync.aligned.m16n8k16.row.col.f32.bf16.bf16.f32 "
        "{%0,%1,%2,%3}, {%4,%5,%6,%7}, {%8,%9}, {%0,%1,%2,%3};"
        : "+f"(d[0]), "+f"(d[1]), "+f"(d[2]), "+f"(d[3])
        : "r"(a[0]), "r"(a[1]), "r"(a[2]), "r"(a[3]), "r"(b[0]), "r"(b[1]));
}
__device__ __forceinline__ void mma_f16(float* d, const uint32_t* a, const uint32_t* b) {
    asm volatile(
        "mma.sync.aligned.m16n8k16.row.col.f32.f16.f16.f32 "
        "{%0,%1,%2,%3}, {%4,%5,%6,%7}, {%8,%9}, {%0,%1,%2,%3};"
        : "+f"(d[0]), "+f"(d[1]), "+f"(d[2]), "+f"(d[3])
        : "r"(a[0]), "r"(a[1]), "r"(a[2]), "r"(a[3]), "r"(b[0]), "r"(b[1]));
}
__device__ __forceinline__ void ldsm4(uint32_t* r, uint32_t a) {
    asm volatile("ldmatrix.sync.aligned.m8n8.x4.shared.b16 {%0,%1,%2,%3}, [%4];"
                 : "=r"(r[0]), "=r"(r[1]), "=r"(r[2]), "=r"(r[3]) : "r"(a));
}

// ---------------- split fp32 -> augmented bf16 [R, 3K] ----------------
template <bool APAT, bool TRANS>
__global__ __launch_bounds__(256) void split_aug(const float* __restrict__ src,
                                                 __nv_bfloat16* __restrict__ dst,
                                                 int Rout, int K, long long sZ, long long dZ) {
    src += blockIdx.y * sZ;
    dst += blockIdx.y * dZ;
    long long idx = (long long)blockIdx.x * 256 + threadIdx.x;
    int row, kp;
    float v0, v1;
    if (TRANS) {
        row = (int)(idx % Rout);
        kp = (int)(idx / Rout) * 2;
        v0 = src[(long long)kp * Rout + row];
        v1 = src[(long long)(kp + 1) * Rout + row];
    } else {
        const int hk = K >> 1;
        row = (int)(idx / hk);
        kp = (int)(idx % hk) * 2;
        v0 = src[(long long)row * K + kp];
        v1 = src[(long long)row * K + kp + 1];
    }
    __nv_bfloat16 h0, l0, h1, l1;
    split2(v0, h0, l0);
    split2(v1, h1, l1);
    __nv_bfloat162 H, L;
    H.x = h0; H.y = h1;
    L.x = l0; L.y = l1;
    __nv_bfloat162* d = (__nv_bfloat162*)(dst + (long long)row * 3 * K);
    d[kp >> 1] = H;
    d[(K + kp) >> 1] = APAT ? H : L;
    d[(2 * K + kp) >> 1] = APAT ? L : H;
}

// ---------------- transpose+convert fp32 -> fp16 [Rout, K] ----------------
__global__ __launch_bounds__(256) void split_h_trans(const float* __restrict__ src,
                                                     __half* __restrict__ dst,
                                                     int Rout, int K, long long sZ, long long dZ) {
    src += blockIdx.y * sZ;
    dst += blockIdx.y * dZ;
    long long idx = (long long)blockIdx.x * 256 + threadIdx.x;
    int row = (int)(idx % Rout);
    int kp = (int)(idx / Rout) * 2;
    __half2 H;
    H.x = __float2half(src[(long long)kp * Rout + row]);
    H.y = __float2half(src[(long long)(kp + 1) * Rout + row]);
    *(__half2*)(dst + (long long)row * K + kp) = H;
}

// ---------------- reduce 4 split-K partials -> B-aug (hi,lo,hi) ----------------
__global__ __launch_bounds__(256) void reduce4_bsplit(const float* __restrict__ p,
                                                      __nv_bfloat16* __restrict__ d) {
    int i = blockIdx.x * 256 + threadIdx.x;
    int e2 = i >> 9;
    int e1 = (i & 511) * 2;
    long long o = (long long)e2 * 1024 + e1;
    float v0 = p[o] + p[o + (1 << 20)] + p[o + (2 << 20)] + p[o + (3 << 20)];
    float v1 = p[o + 1] + p[o + 1 + (1 << 20)] + p[o + 1 + (2 << 20)] + p[o + 1 + (3 << 20)];
    __nv_bfloat16 h0, l0, h1, l1;
    split2(v0, h0, l0);
    split2(v1, h1, l1);
    __nv_bfloat162 H, L;
    H.x = h0; H.y = h1;
    L.x = l0; L.y = l1;
    __nv_bfloat162* q = (__nv_bfloat162*)(d + (long long)e2 * 3072);
    q[e1 >> 1] = H;
    q[(1024 + e1) >> 1] = L;
    q[(2048 + e1) >> 1] = H;
}

// ---------------- pipelined mma.sync GEMM, CTA 128x128, warp 64x32, 3 stages, 2 CTAs/SM --------
// FT: 0 bf16 mma, 1 fp16 mma.
// EPI 0: f32*cscale; EPI 1: bf16 A-aug (hi,hi,lo) stride 3072; EPI 2: fp16 hi-only, stride 1024.
template <int EPI, int FT>
__global__ __launch_bounds__(256, 2)
void gemm_mma(const __nv_bfloat16* __restrict__ A, const __nv_bfloat16* __restrict__ B,
              float* __restrict__ Cf, void* __restrict__ aux,
              int N, int Kp, int bKp, int kiters, float cscale,
              long long aZ, long long bZ, long long cZ) {
    extern __shared__ char smem[];
    const uint32_t sb = smem_u32(smem);
    const int tid = threadIdx.x;
    const int lane = tid & 31, g = lane >> 2, c = lane & 3;
    const int wid = tid >> 5, wm = wid & 1, wn = wid >> 1;

    const char* Ab = (const char*)(A + blockIdx.z * aZ + (long long)(blockIdx.y * 128) * Kp);
    const char* Bb = (const char*)(B + blockIdx.z * bZ + (long long)(blockIdx.x * 128) * bKp);
    const long long arows = (long long)Kp * 2, brows = (long long)bKp * 2;

    uint32_t aOff[4], bOff[2];
#pragma unroll
    for (int i = 0; i < 4; i++)
        aOff[i] = (wm * 64 + i * 16 + (lane & 7) + 8 * ((lane >> 3) & 1)) * ROWB + 16 * ((lane >> 4) & 1);
#pragma unroll
    for (int jp = 0; jp < 2; jp++)
        bOff[jp] = (128 + wn * 32 + jp * 16 + (lane & 7) + 8 * ((lane >> 4) & 1)) * ROWB + 16 * ((lane >> 3) & 1);

    auto load_stage = [&](int s, int ck, bool active) {
        if (active) {
            uint32_t d0 = sb + s * STAGE_B;
            long long off = (long long)ck * 128;
#pragma unroll
            for (int t = 0; t < 4; t++) {
                int idx = tid + 256 * t, r = idx >> 3, sg = (idx & 7) * 16;
                cpasync16(d0 + r * ROWB + sg, Ab + (long long)r * arows + off + sg);
            }
#pragma unroll
            for (int t = 4; t < 8; t++) {
                int idx = tid + 256 * t, r = idx >> 3, sg = (idx & 7) * 16;
                cpasync16(d0 + r * ROWB + sg, Bb + (long long)(r - 128) * brows + off + sg);
            }
        }
        asm volatile("cp.async.commit_group;");
    };

    float acc[4][4][4];
#pragma unroll
    for (int i = 0; i < 4; i++)
#pragma unroll
        for (int j = 0; j < 4; j++)
#pragma unroll
            for (int r = 0; r < 4; r++) acc[i][j][r] = 0.0f;

#pragma unroll
    for (int s = 0; s < 2; s++) load_stage(s, s, s < kiters);

    for (int k = 0; k < kiters; k++) {
        asm volatile("cp.async.wait_group 1;");
        __syncthreads();
        const int nk = k + 2;
        load_stage(nk % 3, nk, nk < kiters);
        const uint32_t sk = sb + (k % 3) * STAGE_B;
#pragma unroll
        for (int ks = 0; ks < 4; ks++) {
            uint32_t af[4][4], bfr[4][2];
#pragma unroll
            for (int i = 0; i < 4; i++) ldsm4(af[i], sk + aOff[i] + ks * 32);
#pragma unroll
            for (int jp = 0; jp < 2; jp++) {
                uint32_t q[4];
                ldsm4(q, sk + bOff[jp] + ks * 32);
                bfr[2 * jp][0] = q[0];
                bfr[2 * jp][1] = q[1];
                bfr[2 * jp + 1][0] = q[2];
                bfr[2 * jp + 1][1] = q[3];
            }
#pragma unroll
            for (int i = 0; i < 4; i++)
#pragma unroll
                for (int j = 0; j < 4; j++) {
                    if (FT) mma_f16(acc[i][j], af[i], bfr[j]);
                    else mma_bf16(acc[i][j], af[i], bfr[j]);
                }
        }
    }

#pragma unroll
    for (int i = 0; i < 4; i++) {
#pragma unroll
        for (int j = 0; j < 4; j++) {
            const int r0 = blockIdx.y * 128 + wm * 64 + i * 16 + g;
            const int n0 = blockIdx.x * 128 + wn * 32 + j * 8 + 2 * c;
            if (EPI == 0) {
                float* Cb = Cf + blockIdx.z * cZ;
                float2 lo, hi;
                lo.x = acc[i][j][0] * cscale; lo.y = acc[i][j][1] * cscale;
                hi.x = acc[i][j][2] * cscale; hi.y = acc[i][j][3] * cscale;
                *(float2*)&Cb[(long long)r0 * N + n0] = lo;
                *(float2*)&Cb[(long long)(r0 + 8) * N + n0] = hi;
            } else if (EPI == 1) {
                __nv_bfloat16* ab = (__nv_bfloat16*)aux + blockIdx.z * cZ;
#pragma unroll
                for (int rr = 0; rr < 2; rr++) {
                    const int row = r0 + 8 * rr;
                    __nv_bfloat16 h0, l0, h1, l1;
                    split2(acc[i][j][2 * rr], h0, l0);
                    split2(acc[i][j][2 * rr + 1], h1, l1);
                    __nv_bfloat162 H, L;
                    H.x = h0; H.y = h1;
                    L.x = l0; L.y = l1;
                    __nv_bfloat162* p2 = (__nv_bfloat162*)(ab + (long long)row * 3072);
                    p2[n0 >> 1] = H;
                    p2[(1024 + n0) >> 1] = H;
                    p2[(2048 + n0) >> 1] = L;
                }
            } else {
                __half* ab = (__half*)aux + blockIdx.z * cZ;
#pragma unroll
                for (int rr = 0; rr < 2; rr++) {
                    const int row = r0 + 8 * rr;
                    __half2 H;
                    H.x = __float2half(acc[i][j][2 * rr]);
                    H.y = __float2half(acc[i][j][2 * rr + 1]);
                    *(__half2*)((__half*)(ab + (long long)row * 1024) + n0) = H;
                }
            }
        }
    }
}

// ---------------- softmax (no /32) -> P fp16 hi-only [row, 2048] ----------------
__global__ __launch_bounds__(256) void softmax_fp16(const float* __restrict__ S,
                                                    __half* __restrict__ pa) {
    const float* row = S + (long long)blockIdx.x * Sq;
    __half* d = pa + (long long)blockIdx.x * 2048;
    const int tid = threadIdx.x;
    float vals[8], m = -INFINITY;
#pragma unroll
    for (int i = 0; i < 4; i++) {
        float2 f = *(const float2*)&row[i * 512 + 2 * tid];
        vals[2 * i] = f.x;
        vals[2 * i + 1] = f.y;
        m = fmaxf(m, fmaxf(f.x, f.y));
    }
    __shared__ float red[256];
    red[tid] = m;
    __syncthreads();
    for (int s = 128; s > 0; s >>= 1) { if (tid < s) red[tid] = fmaxf(red[tid], red[tid + s]); __syncthreads(); }
    m = red[0];
    __syncthreads();
    float sum = 0.f;
#pragma unroll
    for (int i = 0; i < 8; i++) { vals[i] = expf(vals[i] - m); sum += vals[i]; }
    red[tid] = sum;
    __syncthreads();
    for (int s = 128; s > 0; s >>= 1) { if (tid < s) red[tid] += red[tid + s]; __syncthreads(); }
    const float inv = 1.0f / red[0];
#pragma unroll
    for (int i = 0; i < 4; i++) {
        const int j = i * 512 + 2 * tid;
        __half2 H;
        H.x = __float2half(vals[2 * i] * inv);
        H.y = __float2half(vals[2 * i + 1] * inv);
        *(__half2*)(d + j) = H;
    }
}

extern "C" void kernel_launch(void* const* d_in, const int* in_sizes, int n_in,
                              void* d_out, int out_size) {
    const float* values  = (const float*)d_in[0];
    const float* keys    = (const float*)d_in[1];
    const float* queries = (const float*)d_in[2];
    const float* Wv = (const float*)d_in[3];
    const float* Wk = (const float*)d_in[4];
    const float* Wq = (const float*)d_in[5];
    float* out = (float*)d_out;

    __nv_bfloat16 *xa, *wka, *wqb, *mb, *ta, *ka;
    __half *wvh, *va, *pa;
    float *mpart, *sc;
    cudaGetSymbolAddress((void**)&xa, g_xa);
    cudaGetSymbolAddress((void**)&wka, g_wka);
    cudaGetSymbolAddress((void**)&wqb, g_wqb);
    cudaGetSymbolAddress((void**)&mb, g_mb);
    cudaGetSymbolAddress((void**)&wvh, g_wvh);
    cudaGetSymbolAddress((void**)&ta, g_ta);
    cudaGetSymbolAddress((void**)&ka, g_ka);
    cudaGetSymbolAddress((void**)&va, g_va);
    cudaGetSymbolAddress((void**)&pa, g_pa);
    cudaGetSymbolAddress((void**)&mpart, g_mpart);
    cudaGetSymbolAddress((void**)&sc, g_s);

    cudaFuncSetAttribute(gemm_mma<0, 0>, cudaFuncAttributeMaxDynamicSharedMemorySize, SMEM_T);
    cudaFuncSetAttribute(gemm_mma<1, 0>, cudaFuncAttributeMaxDynamicSharedMemorySize, SMEM_T);
    cudaFuncSetAttribute(gemm_mma<2, 1>, cudaFuncAttributeMaxDynamicSharedMemorySize, SMEM_T);
    cudaFuncSetAttribute(gemm_mma<0, 1>, cudaFuncAttributeMaxDynamicSharedMemorySize, SMEM_T);

    // M' = Wk @ Wq^T (split-K=4), bf16 3-term
    split_aug<true, false><<<2048, 256>>>(Wk, wka, 1024, 1024, 0, 0);
    split_aug<false, false><<<2048, 256>>>(Wq, wqb, 1024, 1024, 0, 0);
    gemm_mma<0, 0><<<dim3(8, 8, 4), 256, SMEM_T>>>(wka, wqb, mpart, nullptr,
                                                   1024, 3072, 3072, 12, 1.0f,
                                                   768, 768, 1 << 20);
    reduce4_bsplit<<<2048, 256>>>(mpart, mb);

    // t = x_q @ M'^T -> bf16 A-aug
    split_aug<true, false><<<16384, 256>>>(queries, xa, 8192, 1024, 0, 0);
    gemm_mma<1, 0><<<dim3(8, 64, 1), 256, SMEM_T>>>(xa, mb, nullptr, ta,
                                                    1024, 3072, 3072, 48, 1.0f, 0, 0, 0);

    // scores = t @ x_k^T per batch, bf16 3-term
    split_aug<false, false><<<dim3(4096, 4), 256>>>(keys, ka, 2048, 1024,
                                                    2048LL * 1024, 2048LL * 3072);
    gemm_mma<0, 0><<<dim3(16, 16, 4), 256, SMEM_T>>>(ta, ka, sc, nullptr,
                                                     2048, 3072, 3072, 48, 1.0f,
                                                     2048LL * 3072, 2048LL * 3072, (long long)Sq * Sq);
    // softmax -> P fp16 hi-only
    softmax_fp16<<<Bq * Sq, 256>>>(sc, pa);

    // u = P @ x_v^T per batch, fp16 1-term -> u fp16 in ta
    split_h_trans<<<dim3(4096, 4), 256>>>(values, va, 1024, 2048, 2048LL * 1024, 1024LL * 2048);
    gemm_mma<2, 1><<<dim3(8, 16, 4), 256, SMEM_T>>>((__nv_bfloat16*)pa, (__nv_bfloat16*)va,
                                                    nullptr, ta,
                                                    1024, 2048, 2048, 32, 1.0f,
                                                    2048LL * 2048, 1024LL * 2048, 2048LL * 1024);
    // out = (u @ Wv) / 32, fp16 1-term
    split_h_trans<<<2048, 256>>>(Wv, wvh, 1024, 1024, 0, 0);
    gemm_mma<0, 1><<<dim3(8, 64, 1), 256, SMEM_T>>>(ta, (__nv_bfloat16*)wvh, out, nullptr,
                                                    1024, 1024, 1024, 16, 1.0f / 32.0f,
                                                    0, 0, 0);

    (void)in_sizes; (void)n_in; (void)out_size;
}

// round 12
// speedup vs baseline: 2.2683x; 1.1680x over previous
#include <cuda_runtime.h>
#include <cuda_bf16.h>
#include <cuda_fp16.h>
#include <math.h>
#include <stdint.h>

#define Bq 4
#define Sq 2048
#define Eq 1024
#define ROWB 144
#define STAGE_B (256 * ROWB)      // 128 A rows + 128 B rows
#define SMEM_T (3 * STAGE_B)      // 110592 B -> 2 CTAs/SM

// ---------------- scratch ----------------
__device__ __align__(256) __nv_bfloat16 g_xa[8192LL * 3072];      // x_q A-aug bf16
__device__ __align__(256) __nv_bfloat16 g_wka[1024LL * 3072];     // Wk A-aug
__device__ __align__(256) __nv_bfloat16 g_wqb[1024LL * 3072];     // Wq B-aug
__device__ __align__(256) __nv_bfloat16 g_mb[1024LL * 3072];      // M' B-aug
__device__ __align__(256) __half g_wvh[1024LL * 1024];            // Wv^T fp16
__device__ float g_mpart[4LL * 1024 * 1024];                      // M' split-K partials
__device__ __align__(256) __nv_bfloat16 g_ta[8192LL * 3072];      // t A-aug
__device__ __align__(256) __nv_bfloat16 g_ka[4LL * 2048 * 3072];  // keys B-aug per batch
__device__ __align__(256) __half g_xvh[8192LL * 1024];            // x_v fp16 (A layout)
__device__ float g_v[8192LL * 1024];                              // v = x_v @ Wv, fp32
__device__ float g_s[(size_t)Bq * Sq * Sq];                       // fp32 logits

// ---------------- helpers ----------------
__device__ __forceinline__ uint32_t smem_u32(const void* p) {
    uint32_t a;
    asm("{ .reg .u64 t; cvta.to.shared.u64 t, %1; cvt.u32.u64 %0, t; }" : "=r"(a) : "l"(p));
    return a;
}
__device__ __forceinline__ void cpasync16(uint32_t dst, const void* src) {
    asm volatile("cp.async.cg.shared.global [%0], [%1], 16;" :: "r"(dst), "l"(src));
}
__device__ __forceinline__ void split2(float v, __nv_bfloat16& h, __nv_bfloat16& l) {
    h = __float2bfloat16(v);
    l = __float2bfloat16(v - __bfloat162float(h));
}
__device__ __forceinline__ void mma_bf16(float* d, const uint32_t* a, const uint32_t* b) {
    asm volatile(
        "mma.sync.aligned.m16n8k16.row.col.f32.bf16.bf16.f32 "
        "{%0,%1,%2,%3}, {%4,%5,%6,%7}, {%8,%9}, {%0,%1,%2,%3};"
        : "+f"(d[0]), "+f"(d[1]), "+f"(d[2]), "+f"(d[3])
        : "r"(a[0]), "r"(a[1]), "r"(a[2]), "r"(a[3]), "r"(b[0]), "r"(b[1]));
}
__device__ __forceinline__ void mma_f16(float* d, const uint32_t* a, const uint32_t* b) {
    asm volatile(
        "mma.sync.aligned.m16n8k16.row.col.f32.f16.f16.f32 "
        "{%0,%1,%2,%3}, {%4,%5,%6,%7}, {%8,%9}, {%0,%1,%2,%3};"
        : "+f"(d[0]), "+f"(d[1]), "+f"(d[2]), "+f"(d[3])
        : "r"(a[0]), "r"(a[1]), "r"(a[2]), "r"(a[3]), "r"(b[0]), "r"(b[1]));
}
__device__ __forceinline__ void ldsm4(uint32_t* r, uint32_t a) {
    asm volatile("ldmatrix.sync.aligned.m8n8.x4.shared.b16 {%0,%1,%2,%3}, [%4];"
                 : "=r"(r[0]), "=r"(r[1]), "=r"(r[2]), "=r"(r[3]) : "r"(a));
}

// ---------------- split fp32 -> augmented bf16 [R, 3K] ----------------
template <bool APAT, bool TRANS>
__global__ __launch_bounds__(256) void split_aug(const float* __restrict__ src,
                                                 __nv_bfloat16* __restrict__ dst,
                                                 int Rout, int K, long long sZ, long long dZ) {
    src += blockIdx.y * sZ;
    dst += blockIdx.y * dZ;
    long long idx = (long long)blockIdx.x * 256 + threadIdx.x;
    int row, kp;
    float v0, v1;
    if (TRANS) {
        row = (int)(idx % Rout);
        kp = (int)(idx / Rout) * 2;
        v0 = src[(long long)kp * Rout + row];
        v1 = src[(long long)(kp + 1) * Rout + row];
    } else {
        const int hk = K >> 1;
        row = (int)(idx / hk);
        kp = (int)(idx % hk) * 2;
        v0 = src[(long long)row * K + kp];
        v1 = src[(long long)row * K + kp + 1];
    }
    __nv_bfloat16 h0, l0, h1, l1;
    split2(v0, h0, l0);
    split2(v1, h1, l1);
    __nv_bfloat162 H, L;
    H.x = h0; H.y = h1;
    L.x = l0; L.y = l1;
    __nv_bfloat162* d = (__nv_bfloat162*)(dst + (long long)row * 3 * K);
    d[kp >> 1] = H;
    d[(K + kp) >> 1] = APAT ? H : L;
    d[(2 * K + kp) >> 1] = APAT ? L : H;
}

// ---------------- transpose+convert fp32 -> fp16 [Rout, K] ----------------
__global__ __launch_bounds__(256) void split_h_trans(const float* __restrict__ src,
                                                     __half* __restrict__ dst,
                                                     int Rout, int K, long long sZ, long long dZ) {
    src += blockIdx.y * sZ;
    dst += blockIdx.y * dZ;
    long long idx = (long long)blockIdx.x * 256 + threadIdx.x;
    int row = (int)(idx % Rout);
    int kp = (int)(idx / Rout) * 2;
    __half2 H;
    H.x = __float2half(src[(long long)kp * Rout + row]);
    H.y = __float2half(src[(long long)(kp + 1) * Rout + row]);
    *(__half2*)(dst + (long long)row * K + kp) = H;
}

// ---------------- straight convert fp32 -> fp16 ----------------
__global__ __launch_bounds__(256) void conv_h(const float* __restrict__ src,
                                              __half* __restrict__ dst) {
    long long i = (long long)blockIdx.x * 256 + threadIdx.x;
    float2 f = *(const float2*)&src[2 * i];
    __half2 H;
    H.x = __float2half(f.x);
    H.y = __float2half(f.y);
    *(__half2*)(dst + 2 * i) = H;
}

// ---------------- reduce 4 split-K partials -> B-aug (hi,lo,hi) ----------------
__global__ __launch_bounds__(256) void reduce4_bsplit(const float* __restrict__ p,
                                                      __nv_bfloat16* __restrict__ d) {
    int i = blockIdx.x * 256 + threadIdx.x;
    int e2 = i >> 9;
    int e1 = (i & 511) * 2;
    long long o = (long long)e2 * 1024 + e1;
    float v0 = p[o] + p[o + (1 << 20)] + p[o + (2 << 20)] + p[o + (3 << 20)];
    float v1 = p[o + 1] + p[o + 1 + (1 << 20)] + p[o + 1 + (2 << 20)] + p[o + 1 + (3 << 20)];
    __nv_bfloat16 h0, l0, h1, l1;
    split2(v0, h0, l0);
    split2(v1, h1, l1);
    __nv_bfloat162 H, L;
    H.x = h0; H.y = h1;
    L.x = l0; L.y = l1;
    __nv_bfloat162* q = (__nv_bfloat162*)(d + (long long)e2 * 3072);
    q[e1 >> 1] = H;
    q[(1024 + e1) >> 1] = L;
    q[(2048 + e1) >> 1] = H;
}

// ---------------- pipelined mma.sync GEMM, CTA 128x128, warp 64x32, 3 stages, 2 CTAs/SM --------
// FT: 0 bf16 mma, 1 fp16 mma.
// EPI 0: f32*cscale; EPI 1: bf16 A-aug (hi,hi,lo) stride 3072.
template <int EPI, int FT>
__global__ __launch_bounds__(256, 2)
void gemm_mma(const __nv_bfloat16* __restrict__ A, const __nv_bfloat16* __restrict__ B,
              float* __restrict__ Cf, void* __restrict__ aux,
              int N, int Kp, int bKp, int kiters, float cscale,
              long long aZ, long long bZ, long long cZ) {
    extern __shared__ char smem[];
    const uint32_t sb = smem_u32(smem);
    const int tid = threadIdx.x;
    const int lane = tid & 31, g = lane >> 2, c = lane & 3;
    const int wid = tid >> 5, wm = wid & 1, wn = wid >> 1;

    const char* Ab = (const char*)(A + blockIdx.z * aZ + (long long)(blockIdx.y * 128) * Kp);
    const char* Bb = (const char*)(B + blockIdx.z * bZ + (long long)(blockIdx.x * 128) * bKp);
    const long long arows = (long long)Kp * 2, brows = (long long)bKp * 2;

    uint32_t aOff[4], bOff[2];
#pragma unroll
    for (int i = 0; i < 4; i++)
        aOff[i] = (wm * 64 + i * 16 + (lane & 7) + 8 * ((lane >> 3) & 1)) * ROWB + 16 * ((lane >> 4) & 1);
#pragma unroll
    for (int jp = 0; jp < 2; jp++)
        bOff[jp] = (128 + wn * 32 + jp * 16 + (lane & 7) + 8 * ((lane >> 4) & 1)) * ROWB + 16 * ((lane >> 3) & 1);

    auto load_stage = [&](int s, int ck, bool active) {
        if (active) {
            uint32_t d0 = sb + s * STAGE_B;
            long long off = (long long)ck * 128;
#pragma unroll
            for (int t = 0; t < 4; t++) {
                int idx = tid + 256 * t, r = idx >> 3, sg = (idx & 7) * 16;
                cpasync16(d0 + r * ROWB + sg, Ab + (long long)r * arows + off + sg);
            }
#pragma unroll
            for (int t = 4; t < 8; t++) {
                int idx = tid + 256 * t, r = idx >> 3, sg = (idx & 7) * 16;
                cpasync16(d0 + r * ROWB + sg, Bb + (long long)(r - 128) * brows + off + sg);
            }
        }
        asm volatile("cp.async.commit_group;");
    };

    float acc[4][4][4];
#pragma unroll
    for (int i = 0; i < 4; i++)
#pragma unroll
        for (int j = 0; j < 4; j++)
#pragma unroll
            for (int r = 0; r < 4; r++) acc[i][j][r] = 0.0f;

#pragma unroll
    for (int s = 0; s < 2; s++) load_stage(s, s, s < kiters);

    for (int k = 0; k < kiters; k++) {
        asm volatile("cp.async.wait_group 1;");
        __syncthreads();
        const int nk = k + 2;
        load_stage(nk % 3, nk, nk < kiters);
        const uint32_t sk = sb + (k % 3) * STAGE_B;
#pragma unroll
        for (int ks = 0; ks < 4; ks++) {
            uint32_t af[4][4], bfr[4][2];
#pragma unroll
            for (int i = 0; i < 4; i++) ldsm4(af[i], sk + aOff[i] + ks * 32);
#pragma unroll
            for (int jp = 0; jp < 2; jp++) {
                uint32_t q[4];
                ldsm4(q, sk + bOff[jp] + ks * 32);
                bfr[2 * jp][0] = q[0];
                bfr[2 * jp][1] = q[1];
                bfr[2 * jp + 1][0] = q[2];
                bfr[2 * jp + 1][1] = q[3];
            }
#pragma unroll
            for (int i = 0; i < 4; i++)
#pragma unroll
                for (int j = 0; j < 4; j++) {
                    if (FT) mma_f16(acc[i][j], af[i], bfr[j]);
                    else mma_bf16(acc[i][j], af[i], bfr[j]);
                }
        }
    }

#pragma unroll
    for (int i = 0; i < 4; i++) {
#pragma unroll
        for (int j = 0; j < 4; j++) {
            const int r0 = blockIdx.y * 128 + wm * 64 + i * 16 + g;
            const int n0 = blockIdx.x * 128 + wn * 32 + j * 8 + 2 * c;
            if (EPI == 0) {
                float* Cb = Cf + blockIdx.z * cZ;
                float2 lo, hi;
                lo.x = acc[i][j][0] * cscale; lo.y = acc[i][j][1] * cscale;
                hi.x = acc[i][j][2] * cscale; hi.y = acc[i][j][3] * cscale;
                *(float2*)&Cb[(long long)r0 * N + n0] = lo;
                *(float2*)&Cb[(long long)(r0 + 8) * N + n0] = hi;
            } else {
                __nv_bfloat16* ab = (__nv_bfloat16*)aux + blockIdx.z * cZ;
#pragma unroll
                for (int rr = 0; rr < 2; rr++) {
                    const int row = r0 + 8 * rr;
                    __nv_bfloat16 h0, l0, h1, l1;
                    split2(acc[i][j][2 * rr], h0, l0);
                    split2(acc[i][j][2 * rr + 1], h1, l1);
                    __nv_bfloat162 H, L;
                    H.x = h0; H.y = h1;
                    L.x = l0; L.y = l1;
                    __nv_bfloat162* p2 = (__nv_bfloat162*)(ab + (long long)row * 3072);
                    p2[n0 >> 1] = H;
                    p2[(1024 + n0) >> 1] = H;
                    p2[(2048 + n0) >> 1] = L;
                }
            }
        }
    }
}

// ---------------- fused softmax + sparse PV gather + /32 ----------------
// One CTA per query row. p<=1e-8 dropped (mass bound 2e-5). Deterministic compaction.
__global__ __launch_bounds__(256) void softmax_gather(const float* __restrict__ S,
                                                      const float* __restrict__ V,
                                                      float* __restrict__ out) {
    const int row = blockIdx.x;
    const int b = row >> 11;
    const float* lrow = S + (long long)row * Sq;
    const int tid = threadIdx.x;

    float vals[8], m = -INFINITY;
#pragma unroll
    for (int i = 0; i < 4; i++) {
        float2 f = *(const float2*)&lrow[i * 512 + 2 * tid];
        vals[2 * i] = f.x;
        vals[2 * i + 1] = f.y;
        m = fmaxf(m, fmaxf(f.x, f.y));
    }
    __shared__ float red[256];
    red[tid] = m;
    __syncthreads();
    for (int s = 128; s > 0; s >>= 1) { if (tid < s) red[tid] = fmaxf(red[tid], red[tid + s]); __syncthreads(); }
    m = red[0];
    __syncthreads();
    float sum = 0.f;
#pragma unroll
    for (int i = 0; i < 8; i++) { vals[i] = expf(vals[i] - m); sum += vals[i]; }
    red[tid] = sum;
    __syncthreads();
    for (int s = 128; s > 0; s >>= 1) { if (tid < s) red[tid] += red[tid + s]; __syncthreads(); }
    const float inv = 1.0f / red[0];
    __syncthreads();

    // deterministic compaction of {col : p > 1e-8}
    __shared__ int offs[256];
    __shared__ int list_k[2048];
    __shared__ float list_p[2048];
    int c = 0;
#pragma unroll
    for (int i = 0; i < 8; i++)
        if (vals[i] * inv > 1e-8f) c++;
    offs[tid] = c;
    __syncthreads();
    for (int s = 1; s < 256; s <<= 1) {
        int v2 = (tid >= s) ? offs[tid - s] : 0;
        __syncthreads();
        offs[tid] += v2;
        __syncthreads();
    }
    const int total = offs[255];
    int w = offs[tid] - c;
#pragma unroll
    for (int i = 0; i < 8; i++) {
        float p = vals[i] * inv;
        if (p > 1e-8f) {
            list_k[w] = (i >> 1) * 512 + 2 * tid + (i & 1);
            list_p[w] = p;
            w++;
        }
    }
    __syncthreads();

    // accumulate selected v rows; thread owns out cols [4*tid, 4*tid+4)
    float4 acc = make_float4(0.f, 0.f, 0.f, 0.f);
    const float* Vb = V + (long long)b * Sq * Eq;
    for (int j = 0; j < total; j++) {
        const float p = list_p[j];
        const float4 vv = *(const float4*)&Vb[(long long)list_k[j] * Eq + tid * 4];
        acc.x += p * vv.x;
        acc.y += p * vv.y;
        acc.z += p * vv.z;
        acc.w += p * vv.w;
    }
    const float s32 = 1.0f / 32.0f;
    acc.x *= s32; acc.y *= s32; acc.z *= s32; acc.w *= s32;
    *(float4*)&out[(long long)row * Eq + tid * 4] = acc;
}

extern "C" void kernel_launch(void* const* d_in, const int* in_sizes, int n_in,
                              void* d_out, int out_size) {
    const float* values  = (const float*)d_in[0];
    const float* keys    = (const float*)d_in[1];
    const float* queries = (const float*)d_in[2];
    const float* Wv = (const float*)d_in[3];
    const float* Wk = (const float*)d_in[4];
    const float* Wq = (const float*)d_in[5];
    float* out = (float*)d_out;

    __nv_bfloat16 *xa, *wka, *wqb, *mb, *ta, *ka;
    __half *wvh, *xvh;
    float *mpart, *sc, *vf;
    cudaGetSymbolAddress((void**)&xa, g_xa);
    cudaGetSymbolAddress((void**)&wka, g_wka);
    cudaGetSymbolAddress((void**)&wqb, g_wqb);
    cudaGetSymbolAddress((void**)&mb, g_mb);
    cudaGetSymbolAddress((void**)&wvh, g_wvh);
    cudaGetSymbolAddress((void**)&ta, g_ta);
    cudaGetSymbolAddress((void**)&ka, g_ka);
    cudaGetSymbolAddress((void**)&xvh, g_xvh);
    cudaGetSymbolAddress((void**)&vf, g_v);
    cudaGetSymbolAddress((void**)&mpart, g_mpart);
    cudaGetSymbolAddress((void**)&sc, g_s);

    cudaFuncSetAttribute(gemm_mma<0, 0>, cudaFuncAttributeMaxDynamicSharedMemorySize, SMEM_T);
    cudaFuncSetAttribute(gemm_mma<1, 0>, cudaFuncAttributeMaxDynamicSharedMemorySize, SMEM_T);
    cudaFuncSetAttribute(gemm_mma<0, 1>, cudaFuncAttributeMaxDynamicSharedMemorySize, SMEM_T);

    // M' = Wk @ Wq^T (split-K=4), bf16 3-term
    split_aug<true, false><<<2048, 256>>>(Wk, wka, 1024, 1024, 0, 0);
    split_aug<false, false><<<2048, 256>>>(Wq, wqb, 1024, 1024, 0, 0);
    gemm_mma<0, 0><<<dim3(8, 8, 4), 256, SMEM_T>>>(wka, wqb, mpart, nullptr,
                                                   1024, 3072, 3072, 12, 1.0f,
                                                   768, 768, 1 << 20);
    reduce4_bsplit<<<2048, 256>>>(mpart, mb);

    // v = x_v @ Wv, fp16 1-term -> fp32
    conv_h<<<16384, 256>>>(values, xvh);
    split_h_trans<<<2048, 256>>>(Wv, wvh, 1024, 1024, 0, 0);
    gemm_mma<0, 1><<<dim3(8, 64, 1), 256, SMEM_T>>>((__nv_bfloat16*)xvh, (__nv_bfloat16*)wvh,
                                                    vf, nullptr, 1024, 1024, 1024, 16, 1.0f,
                                                    0, 0, 0);

    // t = x_q @ M'^T -> bf16 A-aug
    split_aug<true, false><<<16384, 256>>>(queries, xa, 8192, 1024, 0, 0);
    gemm_mma<1, 0><<<dim3(8, 64, 1), 256, SMEM_T>>>(xa, mb, nullptr, ta,
                                                    1024, 3072, 3072, 48, 1.0f, 0, 0, 0);

    // scores = t @ x_k^T per batch, bf16 3-term
    split_aug<false, false><<<dim3(4096, 4), 256>>>(keys, ka, 2048, 1024,
                                                    2048LL * 1024, 2048LL * 3072);
    gemm_mma<0, 0><<<dim3(16, 16, 4), 256, SMEM_T>>>(ta, ka, sc, nullptr,
                                                     2048, 3072, 3072, 48, 1.0f,
                                                     2048LL * 3072, 2048LL * 3072, (long long)Sq * Sq);

    // fused softmax + sparse gather + /32 -> out
    softmax_gather<<<Bq * Sq, 256>>>(sc, vf, out);

    (void)in_sizes; (void)n_in; (void)out_size;
}

// round 13
// speedup vs baseline: 2.9713x; 1.3099x over previous
#include <cuda_runtime.h>
#include <cuda_bf16.h>
#include <cuda_fp16.h>
#include <math.h>
#include <stdint.h>

#define Bq 4
#define Sq 2048
#define Eq 1024
#define ROWB 144
#define STAGE_B (256 * ROWB)
#define SMEM_T (3 * STAGE_B)      // 110592 -> 2 CTAs/SM

// ---------------- scratch ----------------
__device__ __align__(256) __nv_bfloat16 g_xa[8192LL * 3072];   // x_q A-aug bf16
__device__ __align__(256) __nv_bfloat16 g_wka[1024LL * 3072];  // Wk A-aug
__device__ __align__(256) __nv_bfloat16 g_wqb[1024LL * 3072];  // Wq B-aug
__device__ __align__(256) __nv_bfloat16 g_mb[1024LL * 3072];   // M' B-aug
__device__ __align__(256) __half g_wvh[1024LL * 1024];         // Wv^T fp16
__device__ float g_mpart[4LL * 1024 * 1024];                   // M' split-K partials
__device__ float g_t32[8192LL * 1024];                         // t fp32
__device__ __align__(256) __half g_th[8192LL * 1024];          // t fp16
__device__ __align__(256) __half g_kh[8192LL * 1024];          // keys fp16
__device__ __align__(256) __half g_xvh[8192LL * 1024];         // x_v fp16
__device__ float g_v[8192LL * 1024];                           // v = x_v @ Wv fp32
__device__ float g_s[(size_t)Bq * Sq * Sq];                    // approx logits fp32

// ---------------- helpers ----------------
__device__ __forceinline__ uint32_t smem_u32(const void* p) {
    uint32_t a;
    asm("{ .reg .u64 t; cvta.to.shared.u64 t, %1; cvt.u32.u64 %0, t; }" : "=r"(a) : "l"(p));
    return a;
}
__device__ __forceinline__ void cpasync16(uint32_t dst, const void* src) {
    asm volatile("cp.async.cg.shared.global [%0], [%1], 16;" :: "r"(dst), "l"(src));
}
__device__ __forceinline__ void split2(float v, __nv_bfloat16& h, __nv_bfloat16& l) {
    h = __float2bfloat16(v);
    l = __float2bfloat16(v - __bfloat162float(h));
}
__device__ __forceinline__ void mma_bf16(float* d, const uint32_t* a, const uint32_t* b) {
    asm volatile(
        "mma.sync.aligned.m16n8k16.row.col.f32.bf16.bf16.f32 "
        "{%0,%1,%2,%3}, {%4,%5,%6,%7}, {%8,%9}, {%0,%1,%2,%3};"
        : "+f"(d[0]), "+f"(d[1]), "+f"(d[2]), "+f"(d[3])
        : "r"(a[0]), "r"(a[1]), "r"(a[2]), "r"(a[3]), "r"(b[0]), "r"(b[1]));
}
__device__ __forceinline__ void mma_f16(float* d, const uint32_t* a, const uint32_t* b) {
    asm volatile(
        "mma.sync.aligned.m16n8k16.row.col.f32.f16.f16.f32 "
        "{%0,%1,%2,%3}, {%4,%5,%6,%7}, {%8,%9}, {%0,%1,%2,%3};"
        : "+f"(d[0]), "+f"(d[1]), "+f"(d[2]), "+f"(d[3])
        : "r"(a[0]), "r"(a[1]), "r"(a[2]), "r"(a[3]), "r"(b[0]), "r"(b[1]));
}
__device__ __forceinline__ void ldsm4(uint32_t* r, uint32_t a) {
    asm volatile("ldmatrix.sync.aligned.m8n8.x4.shared.b16 {%0,%1,%2,%3}, [%4];"
                 : "=r"(r[0]), "=r"(r[1]), "=r"(r[2]), "=r"(r[3]) : "r"(a));
}

// ---------------- split fp32 -> augmented bf16 [R, 3K] ----------------
template <bool APAT, bool TRANS>
__global__ __launch_bounds__(256) void split_aug(const float* __restrict__ src,
                                                 __nv_bfloat16* __restrict__ dst,
                                                 int Rout, int K, long long sZ, long long dZ) {
    src += blockIdx.y * sZ;
    dst += blockIdx.y * dZ;
    long long idx = (long long)blockIdx.x * 256 + threadIdx.x;
    int row, kp;
    float v0, v1;
    if (TRANS) {
        row = (int)(idx % Rout);
        kp = (int)(idx / Rout) * 2;
        v0 = src[(long long)kp * Rout + row];
        v1 = src[(long long)(kp + 1) * Rout + row];
    } else {
        const int hk = K >> 1;
        row = (int)(idx / hk);
        kp = (int)(idx % hk) * 2;
        v0 = src[(long long)row * K + kp];
        v1 = src[(long long)row * K + kp + 1];
    }
    __nv_bfloat16 h0, l0, h1, l1;
    split2(v0, h0, l0);
    split2(v1, h1, l1);
    __nv_bfloat162 H, L;
    H.x = h0; H.y = h1;
    L.x = l0; L.y = l1;
    __nv_bfloat162* d = (__nv_bfloat162*)(dst + (long long)row * 3 * K);
    d[kp >> 1] = H;
    d[(K + kp) >> 1] = APAT ? H : L;
    d[(2 * K + kp) >> 1] = APAT ? L : H;
}

// ---------------- transpose+convert fp32 -> fp16 [Rout, K] ----------------
__global__ __launch_bounds__(256) void split_h_trans(const float* __restrict__ src,
                                                     __half* __restrict__ dst,
                                                     int Rout, int K) {
    long long idx = (long long)blockIdx.x * 256 + threadIdx.x;
    int row = (int)(idx % Rout);
    int kp = (int)(idx / Rout) * 2;
    __half2 H;
    H.x = __float2half(src[(long long)kp * Rout + row]);
    H.y = __float2half(src[(long long)(kp + 1) * Rout + row]);
    *(__half2*)(dst + (long long)row * K + kp) = H;
}

// ---------------- straight convert fp32 -> fp16 ----------------
__global__ __launch_bounds__(256) void conv_h(const float* __restrict__ src,
                                              __half* __restrict__ dst) {
    long long i = (long long)blockIdx.x * 256 + threadIdx.x;
    float2 f = *(const float2*)&src[2 * i];
    __half2 H;
    H.x = __float2half(f.x);
    H.y = __float2half(f.y);
    *(__half2*)(dst + 2 * i) = H;
}

// ---------------- reduce 4 split-K partials -> B-aug (hi,lo,hi) ----------------
__global__ __launch_bounds__(256) void reduce4_bsplit(const float* __restrict__ p,
                                                      __nv_bfloat16* __restrict__ d) {
    int i = blockIdx.x * 256 + threadIdx.x;
    int e2 = i >> 9;
    int e1 = (i & 511) * 2;
    long long o = (long long)e2 * 1024 + e1;
    float v0 = p[o] + p[o + (1 << 20)] + p[o + (2 << 20)] + p[o + (3 << 20)];
    float v1 = p[o + 1] + p[o + 1 + (1 << 20)] + p[o + 1 + (2 << 20)] + p[o + 1 + (3 << 20)];
    __nv_bfloat16 h0, l0, h1, l1;
    split2(v0, h0, l0);
    split2(v1, h1, l1);
    __nv_bfloat162 H, L;
    H.x = h0; H.y = h1;
    L.x = l0; L.y = l1;
    __nv_bfloat162* q = (__nv_bfloat162*)(d + (long long)e2 * 3072);
    q[e1 >> 1] = H;
    q[(1024 + e1) >> 1] = L;
    q[(2048 + e1) >> 1] = H;
}

// ---------------- pipelined mma.sync GEMM, CTA 128x128, warp 64x32, 3 stages, 2 CTAs/SM --------
// FT: 0 bf16, 1 fp16. EPI 0: f32*cscale. EPI 2: f32 + fp16 copy (stride 1024).
template <int EPI, int FT>
__global__ __launch_bounds__(256, 2)
void gemm_mma(const __nv_bfloat16* __restrict__ A, const __nv_bfloat16* __restrict__ B,
              float* __restrict__ Cf, void* __restrict__ aux,
              int N, int Kp, int bKp, int kiters, float cscale,
              long long aZ, long long bZ, long long cZ) {
    extern __shared__ char smem[];
    const uint32_t sb = smem_u32(smem);
    const int tid = threadIdx.x;
    const int lane = tid & 31, g = lane >> 2, c = lane & 3;
    const int wid = tid >> 5, wm = wid & 1, wn = wid >> 1;

    const char* Ab = (const char*)(A + blockIdx.z * aZ + (long long)(blockIdx.y * 128) * Kp);
    const char* Bb = (const char*)(B + blockIdx.z * bZ + (long long)(blockIdx.x * 128) * bKp);
    const long long arows = (long long)Kp * 2, brows = (long long)bKp * 2;

    uint32_t aOff[4], bOff[2];
#pragma unroll
    for (int i = 0; i < 4; i++)
        aOff[i] = (wm * 64 + i * 16 + (lane & 7) + 8 * ((lane >> 3) & 1)) * ROWB + 16 * ((lane >> 4) & 1);
#pragma unroll
    for (int jp = 0; jp < 2; jp++)
        bOff[jp] = (128 + wn * 32 + jp * 16 + (lane & 7) + 8 * ((lane >> 4) & 1)) * ROWB + 16 * ((lane >> 3) & 1);

    auto load_stage = [&](int s, int ck, bool active) {
        if (active) {
            uint32_t d0 = sb + s * STAGE_B;
            long long off = (long long)ck * 128;
#pragma unroll
            for (int t = 0; t < 4; t++) {
                int idx = tid + 256 * t, r = idx >> 3, sg = (idx & 7) * 16;
                cpasync16(d0 + r * ROWB + sg, Ab + (long long)r * arows + off + sg);
            }
#pragma unroll
            for (int t = 4; t < 8; t++) {
                int idx = tid + 256 * t, r = idx >> 3, sg = (idx & 7) * 16;
                cpasync16(d0 + r * ROWB + sg, Bb + (long long)(r - 128) * brows + off + sg);
            }
        }
        asm volatile("cp.async.commit_group;");
    };

    float acc[4][4][4];
#pragma unroll
    for (int i = 0; i < 4; i++)
#pragma unroll
        for (int j = 0; j < 4; j++)
#pragma unroll
            for (int r = 0; r < 4; r++) acc[i][j][r] = 0.0f;

#pragma unroll
    for (int s = 0; s < 2; s++) load_stage(s, s, s < kiters);

    for (int k = 0; k < kiters; k++) {
        asm volatile("cp.async.wait_group 1;");
        __syncthreads();
        const int nk = k + 2;
        load_stage(nk % 3, nk, nk < kiters);
        const uint32_t sk = sb + (k % 3) * STAGE_B;
#pragma unroll
        for (int ks = 0; ks < 4; ks++) {
            uint32_t af[4][4], bfr[4][2];
#pragma unroll
            for (int i = 0; i < 4; i++) ldsm4(af[i], sk + aOff[i] + ks * 32);
#pragma unroll
            for (int jp = 0; jp < 2; jp++) {
                uint32_t q[4];
                ldsm4(q, sk + bOff[jp] + ks * 32);
                bfr[2 * jp][0] = q[0];
                bfr[2 * jp][1] = q[1];
                bfr[2 * jp + 1][0] = q[2];
                bfr[2 * jp + 1][1] = q[3];
            }
#pragma unroll
            for (int i = 0; i < 4; i++)
#pragma unroll
                for (int j = 0; j < 4; j++) {
                    if (FT) mma_f16(acc[i][j], af[i], bfr[j]);
                    else mma_bf16(acc[i][j], af[i], bfr[j]);
                }
        }
    }

#pragma unroll
    for (int i = 0; i < 4; i++) {
#pragma unroll
        for (int j = 0; j < 4; j++) {
            const int r0 = blockIdx.y * 128 + wm * 64 + i * 16 + g;
            const int n0 = blockIdx.x * 128 + wn * 32 + j * 8 + 2 * c;
            float* Cb = Cf + blockIdx.z * cZ;
            float2 lo, hi;
            lo.x = acc[i][j][0] * cscale; lo.y = acc[i][j][1] * cscale;
            hi.x = acc[i][j][2] * cscale; hi.y = acc[i][j][3] * cscale;
            *(float2*)&Cb[(long long)r0 * N + n0] = lo;
            *(float2*)&Cb[(long long)(r0 + 8) * N + n0] = hi;
            if (EPI == 2) {
                __half* ab = (__half*)aux;
#pragma unroll
                for (int rr = 0; rr < 2; rr++) {
                    const int row = r0 + 8 * rr;
                    __half2 H;
                    H.x = __float2half(acc[i][j][2 * rr]);
                    H.y = __float2half(acc[i][j][2 * rr + 1]);
                    *(__half2*)(ab + (long long)row * 1024 + n0) = H;
                }
            }
        }
    }
}

// ---------------- fused: approx-softmax select + exact recompute + sparse PV + /32 ----------------
__global__ __launch_bounds__(256) void softmax_gather2(const float* __restrict__ S,
                                                       const float* __restrict__ T,
                                                       const float* __restrict__ Ky,
                                                       const float* __restrict__ V,
                                                       float* __restrict__ out) {
    const int row = blockIdx.x;
    const int b = row >> 11;
    const int tid = threadIdx.x;
    const int lane = tid & 31, wid = tid >> 5;
    const float* lrow = S + (long long)row * Sq;

    // approx logits: thread owns cols {4t..4t+3, 1024+4t..1024+4t+3}
    float4 f0 = *(const float4*)&lrow[4 * tid];
    float4 f1 = *(const float4*)&lrow[1024 + 4 * tid];
    float vals[8] = {f0.x, f0.y, f0.z, f0.w, f1.x, f1.y, f1.z, f1.w};
    float m = -INFINITY;
#pragma unroll
    for (int i = 0; i < 8; i++) m = fmaxf(m, vals[i]);

    __shared__ float red[256];
    red[tid] = m;
    __syncthreads();
    for (int s = 128; s > 0; s >>= 1) { if (tid < s) red[tid] = fmaxf(red[tid], red[tid + s]); __syncthreads(); }
    m = red[0];
    __syncthreads();

    // candidate selection + deterministic compaction
    const float thresh = m - 20.0f;
    __shared__ int offs[256];
    __shared__ int list_k[1024];
    __shared__ float elog[1024];
    __shared__ float wsum[8];
    int c = 0;
#pragma unroll
    for (int i = 0; i < 8; i++)
        if (vals[i] > thresh) c++;
    offs[tid] = c;
    __syncthreads();
    for (int s = 1; s < 256; s <<= 1) {
        int v2 = (tid >= s) ? offs[tid - s] : 0;
        __syncthreads();
        offs[tid] += v2;
        __syncthreads();
    }
    int total = offs[255];
    if (total > 1024) total = 1024;
    int w = offs[tid] - c;
#pragma unroll
    for (int i = 0; i < 8; i++)
        if (vals[i] > thresh) {
            if (w < 1024) list_k[w] = (i >> 2) * 1024 + 4 * tid + (i & 3);
            w++;
        }
    __syncthreads();

    // exact logits: dot(t_fp32[row], keys[b, k]) — thread owns e in [4t, 4t+4)
    const float4 tv = *(const float4*)&T[(long long)row * Eq + 4 * tid];
    const float* Kb = Ky + (long long)b * Sq * Eq;
    for (int j = 0; j < total; j++) {
        const float4 kv = *(const float4*)&Kb[(long long)list_k[j] * Eq + 4 * tid];
        float part = tv.x * kv.x + tv.y * kv.y + tv.z * kv.z + tv.w * kv.w;
#pragma unroll
        for (int off = 16; off > 0; off >>= 1) part += __shfl_xor_sync(0xffffffffu, part, off);
        if (lane == 0) wsum[wid] = part;
        __syncthreads();
        if (tid == 0) {
            float s = 0.f;
#pragma unroll
            for (int ww = 0; ww < 8; ww++) s += wsum[ww];
            elog[j] = s;
        }
        __syncthreads();
    }

    // exact softmax over candidates
    float me = -INFINITY;
    for (int j = 0; j < total; j++) me = fmaxf(me, elog[j]);
    float sum = 0.f;
    for (int j = 0; j < total; j++) sum += expf(elog[j] - me);
    const float inv = 1.0f / (sum * 32.0f);

    // sparse PV accumulate: thread owns out cols [4t, 4t+4)
    float4 acc = make_float4(0.f, 0.f, 0.f, 0.f);
    const float* Vb = V + (long long)b * Sq * Eq;
    for (int j = 0; j < total; j++) {
        const float p = expf(elog[j] - me) * inv;
        const float4 vv = *(const float4*)&Vb[(long long)list_k[j] * Eq + 4 * tid];
        acc.x += p * vv.x;
        acc.y += p * vv.y;
        acc.z += p * vv.z;
        acc.w += p * vv.w;
    }
    *(float4*)&out[(long long)row * Eq + 4 * tid] = acc;
}

extern "C" void kernel_launch(void* const* d_in, const int* in_sizes, int n_in,
                              void* d_out, int out_size) {
    const float* values  = (const float*)d_in[0];
    const float* keys    = (const float*)d_in[1];
    const float* queries = (const float*)d_in[2];
    const float* Wv = (const float*)d_in[3];
    const float* Wk = (const float*)d_in[4];
    const float* Wq = (const float*)d_in[5];
    float* out = (float*)d_out;

    __nv_bfloat16 *xa, *wka, *wqb, *mb;
    __half *wvh, *th, *kh, *xvh;
    float *mpart, *sc, *vf, *t32;
    cudaGetSymbolAddress((void**)&xa, g_xa);
    cudaGetSymbolAddress((void**)&wka, g_wka);
    cudaGetSymbolAddress((void**)&wqb, g_wqb);
    cudaGetSymbolAddress((void**)&mb, g_mb);
    cudaGetSymbolAddress((void**)&wvh, g_wvh);
    cudaGetSymbolAddress((void**)&th, g_th);
    cudaGetSymbolAddress((void**)&kh, g_kh);
    cudaGetSymbolAddress((void**)&xvh, g_xvh);
    cudaGetSymbolAddress((void**)&vf, g_v);
    cudaGetSymbolAddress((void**)&t32, g_t32);
    cudaGetSymbolAddress((void**)&mpart, g_mpart);
    cudaGetSymbolAddress((void**)&sc, g_s);

    cudaFuncSetAttribute(gemm_mma<0, 0>, cudaFuncAttributeMaxDynamicSharedMemorySize, SMEM_T);
    cudaFuncSetAttribute(gemm_mma<2, 0>, cudaFuncAttributeMaxDynamicSharedMemorySize, SMEM_T);
    cudaFuncSetAttribute(gemm_mma<0, 1>, cudaFuncAttributeMaxDynamicSharedMemorySize, SMEM_T);

    // M' = Wk @ Wq^T (split-K=4), bf16 3-term
    split_aug<true, false><<<2048, 256>>>(Wk, wka, 1024, 1024, 0, 0);
    split_aug<false, false><<<2048, 256>>>(Wq, wqb, 1024, 1024, 0, 0);
    gemm_mma<0, 0><<<dim3(8, 8, 4), 256, SMEM_T>>>(wka, wqb, mpart, nullptr,
                                                   1024, 3072, 3072, 12, 1.0f,
                                                   768, 768, 1 << 20);
    reduce4_bsplit<<<2048, 256>>>(mpart, mb);

    // t = x_q @ M'^T, bf16 3-term -> fp32 + fp16
    split_aug<true, false><<<16384, 256>>>(queries, xa, 8192, 1024, 0, 0);
    gemm_mma<2, 0><<<dim3(8, 64, 1), 256, SMEM_T>>>(xa, mb, t32, th,
                                                    1024, 3072, 3072, 48, 1.0f, 0, 0, 0);

    // approx scores = t_h @ keys_h^T per batch, fp16 1-term
    conv_h<<<16384, 256>>>(keys, kh);
    gemm_mma<0, 1><<<dim3(16, 16, 4), 256, SMEM_T>>>((__nv_bfloat16*)th, (__nv_bfloat16*)kh,
                                                     sc, nullptr,
                                                     2048, 1024, 1024, 16, 1.0f,
                                                     2048LL * 1024, 2048LL * 1024,
                                                     (long long)Sq * Sq);

    // v = x_v @ Wv, fp16 1-term -> fp32
    conv_h<<<16384, 256>>>(values, xvh);
    split_h_trans<<<2048, 256>>>(Wv, wvh, 1024, 1024);
    gemm_mma<0, 1><<<dim3(8, 64, 1), 256, SMEM_T>>>((__nv_bfloat16*)xvh, (__nv_bfloat16*)wvh,
                                                    vf, nullptr, 1024, 1024, 1024, 16, 1.0f,
                                                    0, 0, 0);

    // select + exact recompute + sparse PV + /32
    softmax_gather2<<<Bq * Sq, 256>>>(sc, t32, keys, vf, out);

    (void)in_sizes; (void)n_in; (void)out_size;
}

// round 16
// speedup vs baseline: 2.9924x; 1.0071x over previous
#include <cuda_runtime.h>
#include <cuda_bf16.h>
#include <cuda_fp16.h>
#include <math.h>
#include <stdint.h>

#define Bq 4
#define Sq 2048
#define Eq 1024
#define ROWB 144
#define STAGE_B (256 * ROWB)
#define SMEM_T (3 * STAGE_B)      // 110592 -> 2 CTAs/SM

// ---------------- scratch ----------------
__device__ __align__(256) __nv_bfloat16 g_xa[8192LL * 3072];   // x_q A-aug bf16
__device__ __align__(256) __nv_bfloat16 g_wka[1024LL * 3072];  // Wk A-aug
__device__ __align__(256) __nv_bfloat16 g_wqb[1024LL * 3072];  // Wq B-aug
__device__ __align__(256) __nv_bfloat16 g_mb[1024LL * 3072];   // M' B-aug
__device__ __align__(256) __half g_wvh[1024LL * 1024];         // Wv^T fp16
__device__ float g_mpart[4LL * 1024 * 1024];                   // M' split-K partials
__device__ float g_t32[8192LL * 1024];                         // t fp32
__device__ __align__(256) __half g_th[8192LL * 1024];          // t fp16
__device__ __align__(256) __half g_kh[8192LL * 1024];          // keys fp16
__device__ __align__(256) __half g_xvh[8192LL * 1024];         // x_v fp16
__device__ float g_v[8192LL * 1024];                           // v = x_v @ Wv fp32
__device__ __align__(256) __half g_sh[(size_t)Bq * Sq * Sq];   // approx logits fp16

// ---------------- helpers ----------------
__device__ __forceinline__ uint32_t smem_u32(const void* p) {
    uint32_t a;
    asm("{ .reg .u64 t; cvta.to.shared.u64 t, %1; cvt.u32.u64 %0, t; }" : "=r"(a) : "l"(p));
    return a;
}
__device__ __forceinline__ void cpasync16(uint32_t dst, const void* src) {
    asm volatile("cp.async.cg.shared.global [%0], [%1], 16;" :: "r"(dst), "l"(src));
}
__device__ __forceinline__ void split2(float v, __nv_bfloat16& h, __nv_bfloat16& l) {
    h = __float2bfloat16(v);
    l = __float2bfloat16(v - __bfloat162float(h));
}
__device__ __forceinline__ void mma_bf16(float* d, const uint32_t* a, const uint32_t* b) {
    asm volatile(
        "mma.sync.aligned.m16n8k16.row.col.f32.bf16.bf16.f32 "
        "{%0,%1,%2,%3}, {%4,%5,%6,%7}, {%8,%9}, {%0,%1,%2,%3};"
        : "+f"(d[0]), "+f"(d[1]), "+f"(d[2]), "+f"(d[3])
        : "r"(a[0]), "r"(a[1]), "r"(a[2]), "r"(a[3]), "r"(b[0]), "r"(b[1]));
}
__device__ __forceinline__ void mma_f16(float* d, const uint32_t* a, const uint32_t* b) {
    asm volatile(
        "mma.sync.aligned.m16n8k16.row.col.f32.f16.f16.f32 "
        "{%0,%1,%2,%3}, {%4,%5,%6,%7}, {%8,%9}, {%0,%1,%2,%3};"
        : "+f"(d[0]), "+f"(d[1]), "+f"(d[2]), "+f"(d[3])
        : "r"(a[0]), "r"(a[1]), "r"(a[2]), "r"(a[3]), "r"(b[0]), "r"(b[1]));
}
__device__ __forceinline__ void ldsm4(uint32_t* r, uint32_t a) {
    asm volatile("ldmatrix.sync.aligned.m8n8.x4.shared.b16 {%0,%1,%2,%3}, [%4];"
                 : "=r"(r[0]), "=r"(r[1]), "=r"(r[2]), "=r"(r[3]) : "r"(a));
}

// ---------------- split fp32 -> augmented bf16 [R, 3K] ----------------
template <bool APAT, bool TRANS>
__global__ __launch_bounds__(256) void split_aug(const float* __restrict__ src,
                                                 __nv_bfloat16* __restrict__ dst,
                                                 int Rout, int K, long long sZ, long long dZ) {
    src += blockIdx.y * sZ;
    dst += blockIdx.y * dZ;
    long long idx = (long long)blockIdx.x * 256 + threadIdx.x;
    int row, kp;
    float v0, v1;
    if (TRANS) {
        row = (int)(idx % Rout);
        kp = (int)(idx / Rout) * 2;
        v0 = src[(long long)kp * Rout + row];
        v1 = src[(long long)(kp + 1) * Rout + row];
    } else {
        const int hk = K >> 1;
        row = (int)(idx / hk);
        kp = (int)(idx % hk) * 2;
        v0 = src[(long long)row * K + kp];
        v1 = src[(long long)row * K + kp + 1];
    }
    __nv_bfloat16 h0, l0, h1, l1;
    split2(v0, h0, l0);
    split2(v1, h1, l1);
    __nv_bfloat162 H, L;
    H.x = h0; H.y = h1;
    L.x = l0; L.y = l1;
    __nv_bfloat162* d = (__nv_bfloat162*)(dst + (long long)row * 3 * K);
    d[kp >> 1] = H;
    d[(K + kp) >> 1] = APAT ? H : L;
    d[(2 * K + kp) >> 1] = APAT ? L : H;
}

// ---------------- transpose+convert fp32 -> fp16 [Rout, K] ----------------
__global__ __launch_bounds__(256) void split_h_trans(const float* __restrict__ src,
                                                     __half* __restrict__ dst,
                                                     int Rout, int K) {
    long long idx = (long long)blockIdx.x * 256 + threadIdx.x;
    int row = (int)(idx % Rout);
    int kp = (int)(idx / Rout) * 2;
    __half2 H;
    H.x = __float2half(src[(long long)kp * Rout + row]);
    H.y = __float2half(src[(long long)(kp + 1) * Rout + row]);
    *(__half2*)(dst + (long long)row * K + kp) = H;
}

// ---------------- straight convert fp32 -> fp16 ----------------
__global__ __launch_bounds__(256) void conv_h(const float* __restrict__ src,
                                              __half* __restrict__ dst) {
    long long i = (long long)blockIdx.x * 256 + threadIdx.x;
    float2 f = *(const float2*)&src[2 * i];
    __half2 H;
    H.x = __float2half(f.x);
    H.y = __float2half(f.y);
    *(__half2*)(dst + 2 * i) = H;
}

// ---------------- reduce 4 split-K partials -> B-aug (hi,lo,hi) ----------------
__global__ __launch_bounds__(256) void reduce4_bsplit(const float* __restrict__ p,
                                                      __nv_bfloat16* __restrict__ d) {
    int i = blockIdx.x * 256 + threadIdx.x;
    int e2 = i >> 9;
    int e1 = (i & 511) * 2;
    long long o = (long long)e2 * 1024 + e1;
    float v0 = p[o] + p[o + (1 << 20)] + p[o + (2 << 20)] + p[o + (3 << 20)];
    float v1 = p[o + 1] + p[o + 1 + (1 << 20)] + p[o + 1 + (2 << 20)] + p[o + 1 + (3 << 20)];
    __nv_bfloat16 h0, l0, h1, l1;
    split2(v0, h0, l0);
    split2(v1, h1, l1);
    __nv_bfloat162 H, L;
    H.x = h0; H.y = h1;
    L.x = l0; L.y = l1;
    __nv_bfloat162* q = (__nv_bfloat162*)(d + (long long)e2 * 3072);
    q[e1 >> 1] = H;
    q[(1024 + e1) >> 1] = L;
    q[(2048 + e1) >> 1] = H;
}

// ---------------- pipelined mma.sync GEMM, CTA 128x128, warp 64x32, 3 stages, 2 CTAs/SM --------
// FT: 0 bf16, 1 fp16.
// EPI 0: f32*cscale -> Cf. EPI 2: f32 -> Cf + fp16 copy -> aux (stride 1024). EPI 3: fp16 -> aux.
template <int EPI, int FT>
__global__ __launch_bounds__(256, 2)
void gemm_mma(const __nv_bfloat16* __restrict__ A, const __nv_bfloat16* __restrict__ B,
              float* __restrict__ Cf, void* __restrict__ aux,
              int N, int Kp, int bKp, int kiters, float cscale,
              long long aZ, long long bZ, long long cZ) {
    extern __shared__ char smem[];
    const uint32_t sb = smem_u32(smem);
    const int tid = threadIdx.x;
    const int lane = tid & 31, g = lane >> 2, c = lane & 3;
    const int wid = tid >> 5, wm = wid & 1, wn = wid >> 1;

    const char* Ab = (const char*)(A + blockIdx.z * aZ + (long long)(blockIdx.y * 128) * Kp);
    const char* Bb = (const char*)(B + blockIdx.z * bZ + (long long)(blockIdx.x * 128) * bKp);
    const long long arows = (long long)Kp * 2, brows = (long long)bKp * 2;

    uint32_t aOff[4], bOff[2];
#pragma unroll
    for (int i = 0; i < 4; i++)
        aOff[i] = (wm * 64 + i * 16 + (lane & 7) + 8 * ((lane >> 3) & 1)) * ROWB + 16 * ((lane >> 4) & 1);
#pragma unroll
    for (int jp = 0; jp < 2; jp++)
        bOff[jp] = (128 + wn * 32 + jp * 16 + (lane & 7) + 8 * ((lane >> 4) & 1)) * ROWB + 16 * ((lane >> 3) & 1);

    auto load_stage = [&](int s, int ck, bool active) {
        if (active) {
            uint32_t d0 = sb + s * STAGE_B;
            long long off = (long long)ck * 128;
#pragma unroll
            for (int t = 0; t < 4; t++) {
                int idx = tid + 256 * t, r = idx >> 3, sg = (idx & 7) * 16;
                cpasync16(d0 + r * ROWB + sg, Ab + (long long)r * arows + off + sg);
            }
#pragma unroll
            for (int t = 4; t < 8; t++) {
                int idx = tid + 256 * t, r = idx >> 3, sg = (idx & 7) * 16;
                cpasync16(d0 + r * ROWB + sg, Bb + (long long)(r - 128) * brows + off + sg);
            }
        }
        asm volatile("cp.async.commit_group;");
    };

    float acc[4][4][4];
#pragma unroll
    for (int i = 0; i < 4; i++)
#pragma unroll
        for (int j = 0; j < 4; j++)
#pragma unroll
            for (int r = 0; r < 4; r++) acc[i][j][r] = 0.0f;

#pragma unroll
    for (int s = 0; s < 2; s++) load_stage(s, s, s < kiters);

    for (int k = 0; k < kiters; k++) {
        asm volatile("cp.async.wait_group 1;");
        __syncthreads();
        const int nk = k + 2;
        load_stage(nk % 3, nk, nk < kiters);
        const uint32_t sk = sb + (k % 3) * STAGE_B;
#pragma unroll
        for (int ks = 0; ks < 4; ks++) {
            uint32_t af[4][4], bfr[4][2];
#pragma unroll
            for (int i = 0; i < 4; i++) ldsm4(af[i], sk + aOff[i] + ks * 32);
#pragma unroll
            for (int jp = 0; jp < 2; jp++) {
                uint32_t q[4];
                ldsm4(q, sk + bOff[jp] + ks * 32);
                bfr[2 * jp][0] = q[0];
                bfr[2 * jp][1] = q[1];
                bfr[2 * jp + 1][0] = q[2];
                bfr[2 * jp + 1][1] = q[3];
            }
#pragma unroll
            for (int i = 0; i < 4; i++)
#pragma unroll
                for (int j = 0; j < 4; j++) {
                    if (FT) mma_f16(acc[i][j], af[i], bfr[j]);
                    else mma_bf16(acc[i][j], af[i], bfr[j]);
                }
        }
    }

#pragma unroll
    for (int i = 0; i < 4; i++) {
#pragma unroll
        for (int j = 0; j < 4; j++) {
            const int r0 = blockIdx.y * 128 + wm * 64 + i * 16 + g;
            const int n0 = blockIdx.x * 128 + wn * 32 + j * 8 + 2 * c;
            if (EPI == 3) {
                __half* ab = (__half*)aux + blockIdx.z * cZ;
#pragma unroll
                for (int rr = 0; rr < 2; rr++) {
                    __half2 H;
                    H.x = __float2half(acc[i][j][2 * rr]);
                    H.y = __float2half(acc[i][j][2 * rr + 1]);
                    *(__half2*)(ab + (long long)(r0 + 8 * rr) * N + n0) = H;
                }
            } else {
                float* Cb = Cf + blockIdx.z * cZ;
                float2 lo, hi;
                lo.x = acc[i][j][0] * cscale; lo.y = acc[i][j][1] * cscale;
                hi.x = acc[i][j][2] * cscale; hi.y = acc[i][j][3] * cscale;
                *(float2*)&Cb[(long long)r0 * N + n0] = lo;
                *(float2*)&Cb[(long long)(r0 + 8) * N + n0] = hi;
                if (EPI == 2) {
                    __half* ab = (__half*)aux;
#pragma unroll
                    for (int rr = 0; rr < 2; rr++) {
                        __half2 H;
                        H.x = __float2half(acc[i][j][2 * rr]);
                        H.y = __float2half(acc[i][j][2 * rr + 1]);
                        *(__half2*)(ab + (long long)(r0 + 8 * rr) * 1024 + n0) = H;
                    }
                }
            }
        }
    }
}

// ---------------- fused: select (fp16 approx) + exact recompute (warp-parallel) + sparse PV ----
__global__ __launch_bounds__(256) void softmax_gather3(const __half* __restrict__ S,
                                                       const float* __restrict__ T,
                                                       const float* __restrict__ Ky,
                                                       const float* __restrict__ V,
                                                       float* __restrict__ out) {
    const int row = blockIdx.x;
    const int b = row >> 11;
    const int tid = threadIdx.x;
    const int lane = tid & 31, wid = tid >> 5;
    const __half* lrow = S + (long long)row * Sq;

    // approx logits: thread owns cols {4t..4t+3, 1024+4t..1024+4t+3}
    float vals[8];
    {
        __half2 a0 = *(const __half2*)&lrow[4 * tid];
        __half2 a1 = *(const __half2*)&lrow[4 * tid + 2];
        __half2 b0 = *(const __half2*)&lrow[1024 + 4 * tid];
        __half2 b1 = *(const __half2*)&lrow[1024 + 4 * tid + 2];
        vals[0] = __half2float(a0.x); vals[1] = __half2float(a0.y);
        vals[2] = __half2float(a1.x); vals[3] = __half2float(a1.y);
        vals[4] = __half2float(b0.x); vals[5] = __half2float(b0.y);
        vals[6] = __half2float(b1.x); vals[7] = __half2float(b1.y);
    }
    float m = -INFINITY;
#pragma unroll
    for (int i = 0; i < 8; i++) m = fmaxf(m, vals[i]);

    __shared__ float red[256];
    red[tid] = m;
    __syncthreads();
    for (int s = 128; s > 0; s >>= 1) { if (tid < s) red[tid] = fmaxf(red[tid], red[tid + s]); __syncthreads(); }
    m = red[0];
    __syncthreads();

    // candidate selection + deterministic compaction
    const float thresh = m - 20.0f;
    __shared__ int offs[256];
    __shared__ int list_k[1024];
    __shared__ float elog[1024];
    int c = 0;
#pragma unroll
    for (int i = 0; i < 8; i++)
        if (vals[i] > thresh) c++;
    offs[tid] = c;
    __syncthreads();
    for (int s = 1; s < 256; s <<= 1) {
        int v2 = (tid >= s) ? offs[tid - s] : 0;
        __syncthreads();
        offs[tid] += v2;
        __syncthreads();
    }
    int total = offs[255];
    if (total > 1024) total = 1024;
    int w = offs[tid] - c;
#pragma unroll
    for (int i = 0; i < 8; i++)
        if (vals[i] > thresh) {
            if (w < 1024) list_k[w] = (i >> 2) * 1024 + 4 * tid + (i & 3);
            w++;
        }
    __syncthreads();

    // exact logits: one candidate per warp, lane-strided float4 dot, shfl-tree reduce
    const float* Trow = T + (long long)row * Eq;
    const float* Kb = Ky + (long long)b * Sq * Eq;
    for (int j = wid; j < total; j += 8) {
        const float* kr = Kb + (long long)list_k[j] * Eq;
        float part = 0.f;
#pragma unroll
        for (int e = 0; e < 1024; e += 128) {
            const float4 tv = *(const float4*)&Trow[e + 4 * lane];
            const float4 kv = *(const float4*)&kr[e + 4 * lane];
            part += tv.x * kv.x + tv.y * kv.y + tv.z * kv.z + tv.w * kv.w;
        }
#pragma unroll
        for (int off = 16; off > 0; off >>= 1) part += __shfl_xor_sync(0xffffffffu, part, off);
        if (lane == 0) elog[j] = part;
    }
    __syncthreads();

    // exact softmax over candidates (redundant per-thread; total is tiny)
    float me = -INFINITY;
    for (int j = 0; j < total; j++) me = fmaxf(me, elog[j]);
    float sum = 0.f;
    for (int j = 0; j < total; j++) sum += expf(elog[j] - me);
    const float inv = 1.0f / (sum * 32.0f);

    // sparse PV accumulate: thread owns out cols [4t, 4t+4)
    float4 acc = make_float4(0.f, 0.f, 0.f, 0.f);
    const float* Vb = V + (long long)b * Sq * Eq;
    for (int j = 0; j < total; j++) {
        const float p = expf(elog[j] - me) * inv;
        const float4 vv = *(const float4*)&Vb[(long long)list_k[j] * Eq + 4 * tid];
        acc.x += p * vv.x;
        acc.y += p * vv.y;
        acc.z += p * vv.z;
        acc.w += p * vv.w;
    }
    *(float4*)&out[(long long)row * Eq + 4 * tid] = acc;
}

extern "C" void kernel_launch(void* const* d_in, const int* in_sizes, int n_in,
                              void* d_out, int out_size) {
    const float* values  = (const float*)d_in[0];
    const float* keys    = (const float*)d_in[1];
    const float* queries = (const float*)d_in[2];
    const float* Wv = (const float*)d_in[3];
    const float* Wk = (const float*)d_in[4];
    const float* Wq = (const float*)d_in[5];
    float* out = (float*)d_out;

    __nv_bfloat16 *xa, *wka, *wqb, *mb;
    __half *wvh, *th, *kh, *xvh, *sh;
    float *mpart, *vf, *t32;
    cudaGetSymbolAddress((void**)&xa, g_xa);
    cudaGetSymbolAddress((void**)&wka, g_wka);
    cudaGetSymbolAddress((void**)&wqb, g_wqb);
    cudaGetSymbolAddress((void**)&mb, g_mb);
    cudaGetSymbolAddress((void**)&wvh, g_wvh);
    cudaGetSymbolAddress((void**)&th, g_th);
    cudaGetSymbolAddress((void**)&kh, g_kh);
    cudaGetSymbolAddress((void**)&xvh, g_xvh);
    cudaGetSymbolAddress((void**)&vf, g_v);
    cudaGetSymbolAddress((void**)&t32, g_t32);
    cudaGetSymbolAddress((void**)&mpart, g_mpart);
    cudaGetSymbolAddress((void**)&sh, g_sh);

    cudaFuncSetAttribute(gemm_mma<0, 0>, cudaFuncAttributeMaxDynamicSharedMemorySize, SMEM_T);
    cudaFuncSetAttribute(gemm_mma<2, 0>, cudaFuncAttributeMaxDynamicSharedMemorySize, SMEM_T);
    cudaFuncSetAttribute(gemm_mma<3, 1>, cudaFuncAttributeMaxDynamicSharedMemorySize, SMEM_T);
    cudaFuncSetAttribute(gemm_mma<0, 1>, cudaFuncAttributeMaxDynamicSharedMemorySize, SMEM_T);

    // M' = Wk @ Wq^T (split-K=4), bf16 3-term
    split_aug<true, false><<<2048, 256>>>(Wk, wka, 1024, 1024, 0, 0);
    split_aug<false, false><<<2048, 256>>>(Wq, wqb, 1024, 1024, 0, 0);
    gemm_mma<0, 0><<<dim3(8, 8, 4), 256, SMEM_T>>>(wka, wqb, mpart, nullptr,
                                                   1024, 3072, 3072, 12, 1.0f,
                                                   768, 768, 1 << 20);
    reduce4_bsplit<<<2048, 256>>>(mpart, mb);

    // t = x_q @ M'^T, bf16 3-term -> fp32 + fp16
    split_aug<true, false><<<16384, 256>>>(queries, xa, 8192, 1024, 0, 0);
    gemm_mma<2, 0><<<dim3(8, 64, 1), 256, SMEM_T>>>(xa, mb, t32, th,
                                                    1024, 3072, 3072, 48, 1.0f, 0, 0, 0);

    // approx scores = t_h @ keys_h^T per batch, fp16 1-term -> fp16 logits
    conv_h<<<16384, 256>>>(keys, kh);
    gemm_mma<3, 1><<<dim3(16, 16, 4), 256, SMEM_T>>>((__nv_bfloat16*)th, (__nv_bfloat16*)kh,
                                                     nullptr, sh,
                                                     2048, 1024, 1024, 16, 1.0f,
                                                     2048LL * 1024, 2048LL * 1024,
                                                     (long long)Sq * Sq);

    // v = x_v @ Wv, fp16 1-term -> fp32
    conv_h<<<16384, 256>>>(values, xvh);
    split_h_trans<<<2048, 256>>>(Wv, wvh, 1024, 1024);
    gemm_mma<0, 1><<<dim3(8, 64, 1), 256, SMEM_T>>>((__nv_bfloat16*)xvh, (__nv_bfloat16*)wvh,
                                                    vf, nullptr, 1024, 1024, 1024, 16, 1.0f,
                                                    0, 0, 0);

    // select + exact recompute + sparse PV + /32
    softmax_gather3<<<Bq * Sq, 256>>>(sh, t32, keys, vf, out);

    (void)in_sizes; (void)n_in; (void)out_size;
}

// round 17
// speedup vs baseline: 3.1382x; 1.0487x over previous
#include <cuda_runtime.h>
#include <cuda_bf16.h>
#include <cuda_fp16.h>
#include <math.h>
#include <stdint.h>

#define Bq 4
#define Sq 2048
#define Eq 1024
#define ROWB 144
#define STAGE_B (256 * ROWB)
#define SMEM_T (3 * STAGE_B)      // 110592 -> 2 CTAs/SM

// ---------------- scratch ----------------
__device__ __align__(256) __nv_bfloat16 g_xa[8192LL * 3072];   // x_q A-aug bf16
__device__ __align__(256) __nv_bfloat16 g_wka[1024LL * 3072];  // Wk A-aug
__device__ __align__(256) __nv_bfloat16 g_wqb[1024LL * 3072];  // Wq B-aug
__device__ __align__(256) __nv_bfloat16 g_mb[1024LL * 3072];   // M' B-aug
__device__ __align__(256) __half g_wvh[1024LL * 1024];         // Wv^T fp16
__device__ float g_mpart[4LL * 1024 * 1024];                   // M' split-K partials
__device__ float g_t32[8192LL * 1024];                         // t fp32
__device__ __align__(256) __half g_th[8192LL * 1024];          // t fp16
__device__ __align__(256) __half g_kh[8192LL * 1024];          // keys fp16
__device__ __align__(256) __half g_wh[8192LL * 1024];          // w = P @ x_v, fp16
__device__ __align__(256) __half g_sh[(size_t)Bq * Sq * Sq];   // approx logits fp16

// ---------------- helpers ----------------
__device__ __forceinline__ uint32_t smem_u32(const void* p) {
    uint32_t a;
    asm("{ .reg .u64 t; cvta.to.shared.u64 t, %1; cvt.u32.u64 %0, t; }" : "=r"(a) : "l"(p));
    return a;
}
__device__ __forceinline__ void cpasync16(uint32_t dst, const void* src) {
    asm volatile("cp.async.cg.shared.global [%0], [%1], 16;" :: "r"(dst), "l"(src));
}
__device__ __forceinline__ void split2(float v, __nv_bfloat16& h, __nv_bfloat16& l) {
    h = __float2bfloat16(v);
    l = __float2bfloat16(v - __bfloat162float(h));
}
__device__ __forceinline__ void mma_bf16(float* d, const uint32_t* a, const uint32_t* b) {
    asm volatile(
        "mma.sync.aligned.m16n8k16.row.col.f32.bf16.bf16.f32 "
        "{%0,%1,%2,%3}, {%4,%5,%6,%7}, {%8,%9}, {%0,%1,%2,%3};"
        : "+f"(d[0]), "+f"(d[1]), "+f"(d[2]), "+f"(d[3])
        : "r"(a[0]), "r"(a[1]), "r"(a[2]), "r"(a[3]), "r"(b[0]), "r"(b[1]));
}
__device__ __forceinline__ void mma_f16(float* d, const uint32_t* a, const uint32_t* b) {
    asm volatile(
        "mma.sync.aligned.m16n8k16.row.col.f32.f16.f16.f32 "
        "{%0,%1,%2,%3}, {%4,%5,%6,%7}, {%8,%9}, {%0,%1,%2,%3};"
        : "+f"(d[0]), "+f"(d[1]), "+f"(d[2]), "+f"(d[3])
        : "r"(a[0]), "r"(a[1]), "r"(a[2]), "r"(a[3]), "r"(b[0]), "r"(b[1]));
}
__device__ __forceinline__ void ldsm4(uint32_t* r, uint32_t a) {
    asm volatile("ldmatrix.sync.aligned.m8n8.x4.shared.b16 {%0,%1,%2,%3}, [%4];"
                 : "=r"(r[0]), "=r"(r[1]), "=r"(r[2]), "=r"(r[3]) : "r"(a));
}

// ---------------- split fp32 -> augmented bf16 [R, 3K] ----------------
template <bool APAT, bool TRANS>
__global__ __launch_bounds__(256) void split_aug(const float* __restrict__ src,
                                                 __nv_bfloat16* __restrict__ dst,
                                                 int Rout, int K, long long sZ, long long dZ) {
    src += blockIdx.y * sZ;
    dst += blockIdx.y * dZ;
    long long idx = (long long)blockIdx.x * 256 + threadIdx.x;
    int row, kp;
    float v0, v1;
    if (TRANS) {
        row = (int)(idx % Rout);
        kp = (int)(idx / Rout) * 2;
        v0 = src[(long long)kp * Rout + row];
        v1 = src[(long long)(kp + 1) * Rout + row];
    } else {
        const int hk = K >> 1;
        row = (int)(idx / hk);
        kp = (int)(idx % hk) * 2;
        v0 = src[(long long)row * K + kp];
        v1 = src[(long long)row * K + kp + 1];
    }
    __nv_bfloat16 h0, l0, h1, l1;
    split2(v0, h0, l0);
    split2(v1, h1, l1);
    __nv_bfloat162 H, L;
    H.x = h0; H.y = h1;
    L.x = l0; L.y = l1;
    __nv_bfloat162* d = (__nv_bfloat162*)(dst + (long long)row * 3 * K);
    d[kp >> 1] = H;
    d[(K + kp) >> 1] = APAT ? H : L;
    d[(2 * K + kp) >> 1] = APAT ? L : H;
}

// ---------------- transpose+convert fp32 -> fp16 [Rout, K] ----------------
__global__ __launch_bounds__(256) void split_h_trans(const float* __restrict__ src,
                                                     __half* __restrict__ dst,
                                                     int Rout, int K) {
    long long idx = (long long)blockIdx.x * 256 + threadIdx.x;
    int row = (int)(idx % Rout);
    int kp = (int)(idx / Rout) * 2;
    __half2 H;
    H.x = __float2half(src[(long long)kp * Rout + row]);
    H.y = __float2half(src[(long long)(kp + 1) * Rout + row]);
    *(__half2*)(dst + (long long)row * K + kp) = H;
}

// ---------------- straight convert fp32 -> fp16 ----------------
__global__ __launch_bounds__(256) void conv_h(const float* __restrict__ src,
                                              __half* __restrict__ dst) {
    long long i = (long long)blockIdx.x * 256 + threadIdx.x;
    float2 f = *(const float2*)&src[2 * i];
    __half2 H;
    H.x = __float2half(f.x);
    H.y = __float2half(f.y);
    *(__half2*)(dst + 2 * i) = H;
}

// ---------------- reduce 4 split-K partials -> B-aug (hi,lo,hi) ----------------
__global__ __launch_bounds__(256) void reduce4_bsplit(const float* __restrict__ p,
                                                      __nv_bfloat16* __restrict__ d) {
    int i = blockIdx.x * 256 + threadIdx.x;
    int e2 = i >> 9;
    int e1 = (i & 511) * 2;
    long long o = (long long)e2 * 1024 + e1;
    float v0 = p[o] + p[o + (1 << 20)] + p[o + (2 << 20)] + p[o + (3 << 20)];
    float v1 = p[o + 1] + p[o + 1 + (1 << 20)] + p[o + 1 + (2 << 20)] + p[o + 1 + (3 << 20)];
    __nv_bfloat16 h0, l0, h1, l1;
    split2(v0, h0, l0);
    split2(v1, h1, l1);
    __nv_bfloat162 H, L;
    H.x = h0; H.y = h1;
    L.x = l0; L.y = l1;
    __nv_bfloat162* q = (__nv_bfloat162*)(d + (long long)e2 * 3072);
    q[e1 >> 1] = H;
    q[(1024 + e1) >> 1] = L;
    q[(2048 + e1) >> 1] = H;
}

// ---------------- pipelined mma.sync GEMM, CTA 128x128, warp 64x32, 3 stages, 2 CTAs/SM --------
// FT: 0 bf16, 1 fp16.
// EPI 0: f32*cscale -> Cf. EPI 2: f32 -> Cf + fp16 copy -> aux (stride 1024). EPI 3: fp16 -> aux.
template <int EPI, int FT>
__global__ __launch_bounds__(256, 2)
void gemm_mma(const __nv_bfloat16* __restrict__ A, const __nv_bfloat16* __restrict__ B,
              float* __restrict__ Cf, void* __restrict__ aux,
              int N, int Kp, int bKp, int kiters, float cscale,
              long long aZ, long long bZ, long long cZ) {
    extern __shared__ char smem[];
    const uint32_t sb = smem_u32(smem);
    const int tid = threadIdx.x;
    const int lane = tid & 31, g = lane >> 2, c = lane & 3;
    const int wid = tid >> 5, wm = wid & 1, wn = wid >> 1;

    const char* Ab = (const char*)(A + blockIdx.z * aZ + (long long)(blockIdx.y * 128) * Kp);
    const char* Bb = (const char*)(B + blockIdx.z * bZ + (long long)(blockIdx.x * 128) * bKp);
    const long long arows = (long long)Kp * 2, brows = (long long)bKp * 2;

    uint32_t aOff[4], bOff[2];
#pragma unroll
    for (int i = 0; i < 4; i++)
        aOff[i] = (wm * 64 + i * 16 + (lane & 7) + 8 * ((lane >> 3) & 1)) * ROWB + 16 * ((lane >> 4) & 1);
#pragma unroll
    for (int jp = 0; jp < 2; jp++)
        bOff[jp] = (128 + wn * 32 + jp * 16 + (lane & 7) + 8 * ((lane >> 4) & 1)) * ROWB + 16 * ((lane >> 3) & 1);

    auto load_stage = [&](int s, int ck, bool active) {
        if (active) {
            uint32_t d0 = sb + s * STAGE_B;
            long long off = (long long)ck * 128;
#pragma unroll
            for (int t = 0; t < 4; t++) {
                int idx = tid + 256 * t, r = idx >> 3, sg = (idx & 7) * 16;
                cpasync16(d0 + r * ROWB + sg, Ab + (long long)r * arows + off + sg);
            }
#pragma unroll
            for (int t = 4; t < 8; t++) {
                int idx = tid + 256 * t, r = idx >> 3, sg = (idx & 7) * 16;
                cpasync16(d0 + r * ROWB + sg, Bb + (long long)(r - 128) * brows + off + sg);
            }
        }
        asm volatile("cp.async.commit_group;");
    };

    float acc[4][4][4];
#pragma unroll
    for (int i = 0; i < 4; i++)
#pragma unroll
        for (int j = 0; j < 4; j++)
#pragma unroll
            for (int r = 0; r < 4; r++) acc[i][j][r] = 0.0f;

#pragma unroll
    for (int s = 0; s < 2; s++) load_stage(s, s, s < kiters);

    for (int k = 0; k < kiters; k++) {
        asm volatile("cp.async.wait_group 1;");
        __syncthreads();
        const int nk = k + 2;
        load_stage(nk % 3, nk, nk < kiters);
        const uint32_t sk = sb + (k % 3) * STAGE_B;
#pragma unroll
        for (int ks = 0; ks < 4; ks++) {
            uint32_t af[4][4], bfr[4][2];
#pragma unroll
            for (int i = 0; i < 4; i++) ldsm4(af[i], sk + aOff[i] + ks * 32);
#pragma unroll
            for (int jp = 0; jp < 2; jp++) {
                uint32_t q[4];
                ldsm4(q, sk + bOff[jp] + ks * 32);
                bfr[2 * jp][0] = q[0];
                bfr[2 * jp][1] = q[1];
                bfr[2 * jp + 1][0] = q[2];
                bfr[2 * jp + 1][1] = q[3];
            }
#pragma unroll
            for (int i = 0; i < 4; i++)
#pragma unroll
                for (int j = 0; j < 4; j++) {
                    if (FT) mma_f16(acc[i][j], af[i], bfr[j]);
                    else mma_bf16(acc[i][j], af[i], bfr[j]);
                }
        }
    }

#pragma unroll
    for (int i = 0; i < 4; i++) {
#pragma unroll
        for (int j = 0; j < 4; j++) {
            const int r0 = blockIdx.y * 128 + wm * 64 + i * 16 + g;
            const int n0 = blockIdx.x * 128 + wn * 32 + j * 8 + 2 * c;
            if (EPI == 3) {
                __half* ab = (__half*)aux + blockIdx.z * cZ;
#pragma unroll
                for (int rr = 0; rr < 2; rr++) {
                    __half2 H;
                    H.x = __float2half(acc[i][j][2 * rr]);
                    H.y = __float2half(acc[i][j][2 * rr + 1]);
                    *(__half2*)(ab + (long long)(r0 + 8 * rr) * N + n0) = H;
                }
            } else {
                float* Cb = Cf + blockIdx.z * cZ;
                float2 lo, hi;
                lo.x = acc[i][j][0] * cscale; lo.y = acc[i][j][1] * cscale;
                hi.x = acc[i][j][2] * cscale; hi.y = acc[i][j][3] * cscale;
                *(float2*)&Cb[(long long)r0 * N + n0] = lo;
                *(float2*)&Cb[(long long)(r0 + 8) * N + n0] = hi;
                if (EPI == 2) {
                    __half* ab = (__half*)aux;
#pragma unroll
                    for (int rr = 0; rr < 2; rr++) {
                        __half2 H;
                        H.x = __float2half(acc[i][j][2 * rr]);
                        H.y = __float2half(acc[i][j][2 * rr + 1]);
                        *(__half2*)(ab + (long long)(r0 + 8 * rr) * 1024 + n0) = H;
                    }
                }
            }
        }
    }
}

// ---------------- fused: select + exact recompute + sparse w = P @ x_v (fp16 out) ----------------
__global__ __launch_bounds__(256) void softmax_gather4(const __half* __restrict__ S,
                                                       const float* __restrict__ T,
                                                       const float* __restrict__ Ky,
                                                       const float* __restrict__ Xv,
                                                       __half* __restrict__ W) {
    const int row = blockIdx.x;
    const int b = row >> 11;
    const int tid = threadIdx.x;
    const int lane = tid & 31, wid = tid >> 5;
    const __half* lrow = S + (long long)row * Sq;

    // approx logits: thread owns cols {4t..4t+3, 1024+4t..1024+4t+3}
    float vals[8];
    {
        __half2 a0 = *(const __half2*)&lrow[4 * tid];
        __half2 a1 = *(const __half2*)&lrow[4 * tid + 2];
        __half2 b0 = *(const __half2*)&lrow[1024 + 4 * tid];
        __half2 b1 = *(const __half2*)&lrow[1024 + 4 * tid + 2];
        vals[0] = __half2float(a0.x); vals[1] = __half2float(a0.y);
        vals[2] = __half2float(a1.x); vals[3] = __half2float(a1.y);
        vals[4] = __half2float(b0.x); vals[5] = __half2float(b0.y);
        vals[6] = __half2float(b1.x); vals[7] = __half2float(b1.y);
    }
    float m = -INFINITY;
#pragma unroll
    for (int i = 0; i < 8; i++) m = fmaxf(m, vals[i]);

    __shared__ float red[256];
    red[tid] = m;
    __syncthreads();
    for (int s = 128; s > 0; s >>= 1) { if (tid < s) red[tid] = fmaxf(red[tid], red[tid + s]); __syncthreads(); }
    m = red[0];
    __syncthreads();

    // candidate selection + deterministic compaction (drop mass <= 2048*e^-17 = 8.5e-5)
    const float thresh = m - 17.0f;
    __shared__ int offs[256];
    __shared__ int list_k[1024];
    __shared__ float elog[1024];
    int c = 0;
#pragma unroll
    for (int i = 0; i < 8; i++)
        if (vals[i] > thresh) c++;
    offs[tid] = c;
    __syncthreads();
    for (int s = 1; s < 256; s <<= 1) {
        int v2 = (tid >= s) ? offs[tid - s] : 0;
        __syncthreads();
        offs[tid] += v2;
        __syncthreads();
    }
    int total = offs[255];
    if (total > 1024) total = 1024;
    int w = offs[tid] - c;
#pragma unroll
    for (int i = 0; i < 8; i++)
        if (vals[i] > thresh) {
            if (w < 1024) list_k[w] = (i >> 2) * 1024 + 4 * tid + (i & 3);
            w++;
        }
    __syncthreads();

    // exact logits: one candidate per warp, lane-strided float4 dot, shfl-tree reduce
    const float* Trow = T + (long long)row * Eq;
    const float* Kb = Ky + (long long)b * Sq * Eq;
    for (int j = wid; j < total; j += 8) {
        const float* kr = Kb + (long long)list_k[j] * Eq;
        float part = 0.f;
#pragma unroll
        for (int e = 0; e < 1024; e += 128) {
            const float4 tv = *(const float4*)&Trow[e + 4 * lane];
            const float4 kv = *(const float4*)&kr[e + 4 * lane];
            part += tv.x * kv.x + tv.y * kv.y + tv.z * kv.z + tv.w * kv.w;
        }
#pragma unroll
        for (int off = 16; off > 0; off >>= 1) part += __shfl_xor_sync(0xffffffffu, part, off);
        if (lane == 0) elog[j] = part;
    }
    __syncthreads();

    // exact softmax over candidates (redundant per-thread; total is tiny)
    float me = -INFINITY;
    for (int j = 0; j < total; j++) me = fmaxf(me, elog[j]);
    float sum = 0.f;
    for (int j = 0; j < total; j++) sum += expf(elog[j] - me);
    const float inv = 1.0f / sum;

    // sparse accumulate w = sum p * x_v[k]: thread owns cols [4t, 4t+4)
    float4 acc = make_float4(0.f, 0.f, 0.f, 0.f);
    const float* Vb = Xv + (long long)b * Sq * Eq;
    for (int j = 0; j < total; j++) {
        const float p = expf(elog[j] - me) * inv;
        const float4 vv = *(const float4*)&Vb[(long long)list_k[j] * Eq + 4 * tid];
        acc.x += p * vv.x;
        acc.y += p * vv.y;
        acc.z += p * vv.z;
        acc.w += p * vv.w;
    }
    __half2 H0, H1;
    H0.x = __float2half(acc.x);
    H0.y = __float2half(acc.y);
    H1.x = __float2half(acc.z);
    H1.y = __float2half(acc.w);
    __half* wr = W + (long long)row * Eq + 4 * tid;
    *(__half2*)wr = H0;
    *(__half2*)(wr + 2) = H1;
}

extern "C" void kernel_launch(void* const* d_in, const int* in_sizes, int n_in,
                              void* d_out, int out_size) {
    const float* values  = (const float*)d_in[0];
    const float* keys    = (const float*)d_in[1];
    const float* queries = (const float*)d_in[2];
    const float* Wv = (const float*)d_in[3];
    const float* Wk = (const float*)d_in[4];
    const float* Wq = (const float*)d_in[5];
    float* out = (float*)d_out;

    __nv_bfloat16 *xa, *wka, *wqb, *mb;
    __half *wvh, *th, *kh, *wh, *sh;
    float *mpart, *t32;
    cudaGetSymbolAddress((void**)&xa, g_xa);
    cudaGetSymbolAddress((void**)&wka, g_wka);
    cudaGetSymbolAddress((void**)&wqb, g_wqb);
    cudaGetSymbolAddress((void**)&mb, g_mb);
    cudaGetSymbolAddress((void**)&wvh, g_wvh);
    cudaGetSymbolAddress((void**)&th, g_th);
    cudaGetSymbolAddress((void**)&kh, g_kh);
    cudaGetSymbolAddress((void**)&wh, g_wh);
    cudaGetSymbolAddress((void**)&t32, g_t32);
    cudaGetSymbolAddress((void**)&mpart, g_mpart);
    cudaGetSymbolAddress((void**)&sh, g_sh);

    cudaFuncSetAttribute(gemm_mma<0, 0>, cudaFuncAttributeMaxDynamicSharedMemorySize, SMEM_T);
    cudaFuncSetAttribute(gemm_mma<2, 0>, cudaFuncAttributeMaxDynamicSharedMemorySize, SMEM_T);
    cudaFuncSetAttribute(gemm_mma<3, 1>, cudaFuncAttributeMaxDynamicSharedMemorySize, SMEM_T);
    cudaFuncSetAttribute(gemm_mma<0, 1>, cudaFuncAttributeMaxDynamicSharedMemorySize, SMEM_T);

    // M' = Wk @ Wq^T (split-K=4), bf16 3-term
    split_aug<true, false><<<2048, 256>>>(Wk, wka, 1024, 1024, 0, 0);
    split_aug<false, false><<<2048, 256>>>(Wq, wqb, 1024, 1024, 0, 0);
    gemm_mma<0, 0><<<dim3(8, 8, 4), 256, SMEM_T>>>(wka, wqb, mpart, nullptr,
                                                   1024, 3072, 3072, 12, 1.0f,
                                                   768, 768, 1 << 20);
    reduce4_bsplit<<<2048, 256>>>(mpart, mb);

    // t = x_q @ M'^T, bf16 3-term -> fp32 + fp16
    split_aug<true, false><<<16384, 256>>>(queries, xa, 8192, 1024, 0, 0);
    gemm_mma<2, 0><<<dim3(8, 64, 1), 256, SMEM_T>>>(xa, mb, t32, th,
                                                    1024, 3072, 3072, 48, 1.0f, 0, 0, 0);

    // approx scores = t_h @ keys_h^T per batch, fp16 1-term -> fp16 logits
    conv_h<<<16384, 256>>>(keys, kh);
    gemm_mma<3, 1><<<dim3(16, 16, 4), 256, SMEM_T>>>((__nv_bfloat16*)th, (__nv_bfloat16*)kh,
                                                     nullptr, sh,
                                                     2048, 1024, 1024, 16, 1.0f,
                                                     2048LL * 1024, 2048LL * 1024,
                                                     (long long)Sq * Sq);

    // select + exact recompute + sparse w = P @ x_v (fp16)
    softmax_gather4<<<Bq * Sq, 256>>>(sh, t32, keys, values, wh);

    // out = (w @ Wv) / 32, fp16 1-term
    split_h_trans<<<2048, 256>>>(Wv, wvh, 1024, 1024);
    gemm_mma<0, 1><<<dim3(8, 64, 1), 256, SMEM_T>>>((__nv_bfloat16*)wh, (__nv_bfloat16*)wvh,
                                                    out, nullptr, 1024, 1024, 1024, 16,
                                                    1.0f / 32.0f, 0, 0, 0);

    (void)in_sizes; (void)n_in; (void)out_size;
}